// round 8
// baseline (speedup 1.0000x reference)
#include <cuda_runtime.h>

#define B_ 32
#define T_ 128
#define N_ 128
#define M_ 64
#define NT_ 192

// ---------------- device scratch (no allocations allowed) ----------------
__device__ float g_V[B_ * N_ * N_];
__device__ float g_v[B_ * N_];
__device__ float g_w[B_ * N_];
__device__ float g_VF[B_ * N_ * NT_];
__device__ float g_Qxx[B_ * N_ * N_];
__device__ float g_Qu[B_ * M_ * NT_];   // rows 0..63: cols 0..127 = Qux, 128..191 = Quu
__device__ float g_qhat[B_ * NT_];
__device__ float g_K[(size_t)T_ * B_ * M_ * N_];
__device__ float g_k[T_ * B_ * M_];

#define FMA16(a, bq)                                                                   \
    acc[0][0] += a.x * bq.x; acc[0][1] += a.x * bq.y; acc[0][2] += a.x * bq.z; acc[0][3] += a.x * bq.w; \
    acc[1][0] += a.y * bq.x; acc[1][1] += a.y * bq.y; acc[1][2] += a.y * bq.z; acc[1][3] += a.y * bq.w; \
    acc[2][0] += a.z * bq.x; acc[2][1] += a.z * bq.y; acc[2][2] += a.z * bq.z; acc[2][3] += a.z * bq.w; \
    acc[3][0] += a.w * bq.x; acc[3][1] += a.w * bq.y; acc[3][2] += a.w * bq.z; acc[3][3] += a.w * bq.w;

// ---------------- init ----------------
__global__ void kzero() {
    int idx = blockIdx.x * 256 + threadIdx.x;
    if (idx < B_ * N_ * N_) g_V[idx] = 0.0f;
    if (idx < B_ * N_) g_v[idx] = 0.0f;
}

// ---------------- k1: VF = V @ [A|B]  (uses V symmetry), w = V c + v ----------------
__global__ __launch_bounds__(256) void k1_VF(const float* __restrict__ A,
                                             const float* __restrict__ Bm,
                                             const float* __restrict__ c1, int t) {
    int b = blockIdx.y;
    int bx = blockIdx.x;
    int tid = threadIdx.x;
    const float* Vb = g_V + b * N_ * N_;
    size_t bt = (size_t)b * T_ + t;

    if (bx == 6) {  // w = V c + v  (V symmetric -> coalesced column read)
        __shared__ float cs[128];
        if (tid < 128) cs[tid] = c1[bt * 128 + tid];
        __syncthreads();
        if (tid < 128) {
            float acc = g_v[b * 128 + tid];
#pragma unroll 8
            for (int m = 0; m < 128; m++) acc += Vb[m * 128 + tid] * cs[m];
            g_w[b * 128 + tid] = acc;
        }
        return;
    }

    int tr = bx / 3, tc = bx % 3;
    int rb = tr * 64, cb = tc * 64;
    const float* Fsrc; int ldF, coff;
    if (cb < 128) { Fsrc = A + bt * (size_t)(N_ * N_); ldF = 128; coff = cb; }
    else          { Fsrc = Bm + bt * (size_t)(N_ * M_); ldF = 64;  coff = 0;  }

    __shared__ float As[16][64];
    __shared__ float Bs[16][64];
    int tx = tid & 15, ty = tid >> 4;
    float acc[4][4] = {};

    for (int kb = 0; kb < 8; kb++) {
        int k = kb * 16 + ty;
        // V symmetric: V[row][k] == V[k][row]
        *(float4*)&As[ty][tx * 4] = *(const float4*)(Vb + k * 128 + rb + tx * 4);
        *(float4*)&Bs[ty][tx * 4] = *(const float4*)(Fsrc + (size_t)k * ldF + coff + tx * 4);
        __syncthreads();
#pragma unroll
        for (int kk = 0; kk < 16; kk++) {
            float4 a = *(float4*)&As[kk][ty * 4];
            float4 bq = *(float4*)&Bs[kk][tx * 4];
            FMA16(a, bq)
        }
        __syncthreads();
    }
    float* outp = g_VF + b * N_ * NT_;
#pragma unroll
    for (int i = 0; i < 4; i++) {
        *(float4*)(outp + (rb + ty * 4 + i) * NT_ + cb + tx * 4) =
            make_float4(acc[i][0], acc[i][1], acc[i][2], acc[i][3]);
    }
}

// ---------------- k2: Qxx = Qxx + A^T VF ; [Qux|Quu] = Q_u + B^T VF ; qhat ----------------
__global__ __launch_bounds__(256) void k2_Qhat(const float* __restrict__ A,
                                               const float* __restrict__ Bm,
                                               const float* __restrict__ Q,
                                               const float* __restrict__ p, int t) {
    int b = blockIdx.y, bx = blockIdx.x, tid = threadIdx.x;
    size_t bt = (size_t)b * T_ + t;

    if (bx == 7) {  // qhat = p + F^T w
        __shared__ float ws[128];
        if (tid < 128) ws[tid] = g_w[b * 128 + tid];
        __syncthreads();
        if (tid < 192) {
            float acc = p[bt * NT_ + tid];
            if (tid < 128) {
                const float* Ab = A + bt * (size_t)(N_ * N_);
#pragma unroll 4
                for (int n = 0; n < 128; n++) acc += Ab[n * 128 + tid] * ws[n];
            } else {
                const float* Bb = Bm + bt * (size_t)(N_ * M_);
                int j = tid - 128;
#pragma unroll 4
                for (int n = 0; n < 128; n++) acc += Bb[n * 64 + j] * ws[n];
            }
            g_qhat[b * NT_ + tid] = acc;
        }
        return;
    }

    bool isQxx = bx < 4;
    int ib, jb; const float* Asrc; int lda, aoff;
    if (isQxx) { ib = (bx >> 1) * 64; jb = (bx & 1) * 64; Asrc = A + bt * (size_t)(N_ * N_); lda = 128; aoff = ib; }
    else       { ib = 0; jb = (bx - 4) * 64; Asrc = Bm + bt * (size_t)(N_ * M_); lda = 64; aoff = 0; }

    __shared__ float As[16][64];
    __shared__ float Bs[16][64];
    int tx = tid & 15, ty = tid >> 4;
    const float* VFb = g_VF + b * N_ * NT_;
    float acc[4][4] = {};

    for (int kb = 0; kb < 8; kb++) {
        int k = kb * 16 + ty;
        *(float4*)&As[ty][tx * 4] = *(const float4*)(Asrc + (size_t)k * lda + aoff + tx * 4);
        *(float4*)&Bs[ty][tx * 4] = *(const float4*)(VFb + k * NT_ + jb + tx * 4);
        __syncthreads();
#pragma unroll
        for (int kk = 0; kk < 16; kk++) {
            float4 a = *(float4*)&As[kk][ty * 4];
            float4 bq = *(float4*)&Bs[kk][tx * 4];
            FMA16(a, bq)
        }
        __syncthreads();
    }

    const float* Qb = Q + bt * (size_t)(NT_ * NT_);
    if (isQxx) {
        float* outp = g_Qxx + b * N_ * N_;
#pragma unroll
        for (int i = 0; i < 4; i++) {
            int r = ib + ty * 4 + i, cc = jb + tx * 4;
            float4 q4 = *(const float4*)(Qb + (size_t)r * NT_ + cc);
            *(float4*)(outp + r * N_ + cc) =
                make_float4(acc[i][0] + q4.x, acc[i][1] + q4.y, acc[i][2] + q4.z, acc[i][3] + q4.w);
        }
    } else {
        float* outp = g_Qu + b * M_ * NT_;
#pragma unroll
        for (int i = 0; i < 4; i++) {
            int r = ty * 4 + i, cc = jb + tx * 4;
            float4 q4 = *(const float4*)(Qb + (size_t)(128 + r) * NT_ + cc);
            *(float4*)(outp + r * NT_ + cc) =
                make_float4(acc[i][0] + q4.x, acc[i][1] + q4.y, acc[i][2] + q4.z, acc[i][3] + q4.w);
        }
    }
}

// ---------------- k3: blocked Cholesky(Quu) + block-parallel 129-RHS solve -> K, k, vn ----------------
// Dynamic smem layout:
//   sL   [64*68]  : L in lower triangle (upper untouched; L^T read directly via broadcast)
//   sR   [64*132] : RHS (cols 0..127 = Qux, col 128 = qu, 129..131 junk); solved IN PLACE
//   sPT  [16*66]  : transposed panel for Cholesky trailing update
//   sInvD[64], sk[64]
#define SM_L   0
#define SM_R   (64 * 68)
#define SM_PT  (SM_R + 64 * 132)
#define SM_ID  (SM_PT + 16 * 66)
#define SM_K   (SM_ID + 64)
#define SM_TOT (SM_K + 64)   // floats

__global__ __launch_bounds__(512) void k3_solve(int t) {
    extern __shared__ __align__(16) float sm[];
    float* sL = sm + SM_L;
    float* sR = sm + SM_R;
    float* sPT = sm + SM_PT;
    float* sInvD = sm + SM_ID;
    float* sk = sm + SM_K;

    int b = blockIdx.x, tid = threadIdx.x;
    const float* Qub = g_Qu + b * M_ * NT_;

    // stage Quu into sL and RHS into sR (coalesced, full CTA)
    for (int idx = tid; idx < 64 * 64; idx += 512) {
        int i = idx >> 6, j = idx & 63;
        sL[i * 68 + j] = Qub[i * NT_ + 128 + j];
    }
    for (int idx = tid; idx < 64 * 128; idx += 512) {
        int i = idx >> 7, c = idx & 127;
        sR[i * 132 + c] = Qub[i * NT_ + c];
    }
    if (tid < 64) sR[tid * 132 + 128] = g_qhat[b * NT_ + 128 + tid];
    __syncthreads();

    // ---- blocked lower Cholesky, 16-wide panels ----
    for (int kb = 0; kb < 64; kb += 16) {
        // 1) factor 16x16 diagonal block in registers via shfl (warp 0)
        if (tid < 32) {
            int l = tid & 15;
            int row = kb + l;
            float a[16];
#pragma unroll
            for (int i = 0; i < 16; i++) a[i] = sL[row * 68 + kb + i];
#pragma unroll
            for (int i = 0; i < 16; i++) {
                float aii = __shfl_sync(0xffffffffu, a[i], i);
                float dinv = rsqrtf(aii);
                a[i] *= dinv;
                if (tid == i) sInvD[kb + i] = dinv;
#pragma unroll
                for (int c = i + 1; c < 16; c++) {
                    float lci = __shfl_sync(0xffffffffu, a[i], c);
                    a[c] -= a[i] * lci;
                }
            }
            if (tid < 16) {
#pragma unroll
                for (int i = 0; i < 16; i++)
                    if (i <= l) sL[row * 68 + kb + i] = a[i];
            }
        }
        __syncthreads();

        int rem = 48 - kb;  // panel rows below the diagonal block
        if (rem > 0) {
            // 2) panel solve: one thread per row r = kb+16..63
            if (tid < rem) {
                int r = kb + 16 + tid;
                float a[16];
#pragma unroll
                for (int i = 0; i < 16; i++) a[i] = sL[r * 68 + kb + i];
#pragma unroll
                for (int i = 0; i < 16; i++) {
                    float s = a[i];
#pragma unroll
                    for (int m = 0; m < i; m++) s -= a[m] * sL[(kb + i) * 68 + kb + m];
                    a[i] = s * sInvD[kb + i];
                }
#pragma unroll
                for (int i = 0; i < 16; i++) {
                    sL[r * 68 + kb + i] = a[i];
                    sPT[i * 66 + r] = a[i];   // transposed copy for the update
                }
            }
            __syncthreads();

            // 3) trailing rank-16 update (reads via sPT: conflict-free)
            int total = rem * 64;
            for (int idx = tid; idx < total; idx += 512) {
                int jr = kb + 16 + (idx >> 6);
                int c = idx & 63;
                if (c >= kb + 16 && c <= jr) {
                    float s = sL[jr * 68 + c];
#pragma unroll
                    for (int m = 0; m < 16; m++)
                        s -= sPT[m * 66 + jr] * sPT[m * 66 + c];
                    sL[jr * 68 + c] = s;
                }
            }
            __syncthreads();
        }
    }

    // ---- block-parallel forward substitution: L y = rhs (in place in sR) ----
    for (int jb = 0; jb < 4; jb++) {
        int base = jb * 16;
        if (tid < 132) {
            int c = tid;
            float yl[16];
#pragma unroll
            for (int r = 0; r < 16; r++) yl[r] = sR[(base + r) * 132 + c];
#pragma unroll
            for (int r = 0; r < 16; r++) {
                float s = yl[r];
#pragma unroll
                for (int m = 0; m < r; m++) s -= sL[(base + r) * 68 + base + m] * yl[m];
                yl[r] = s * sInvD[base + r];
                sR[(base + r) * 132 + c] = yl[r];
            }
        }
        __syncthreads();
        int nr = 48 - base;
        if (nr > 0) {
            int total = nr * 132;
            for (int idx = tid; idx < total; idx += 512) {
                int r = base + 16 + idx / 132;
                int c = idx % 132;
                float s = sR[r * 132 + c];
#pragma unroll
                for (int m = 0; m < 16; m++)
                    s -= sL[r * 68 + base + m] * sR[(base + m) * 132 + c];
                sR[r * 132 + c] = s;
            }
        }
        __syncthreads();
    }

    // ---- block-parallel backward substitution: L^T x = y (L read transposed) ----
    for (int jb = 3; jb >= 0; jb--) {
        int base = jb * 16;
        if (tid < 132) {
            int c = tid;
            float yl[16];
#pragma unroll
            for (int r = 0; r < 16; r++) yl[r] = sR[(base + r) * 132 + c];
#pragma unroll
            for (int r = 15; r >= 0; r--) {
                float s = yl[r];
#pragma unroll
                for (int m = r + 1; m < 16; m++) s -= sL[(base + m) * 68 + base + r] * yl[m];
                yl[r] = s * sInvD[base + r];
                sR[(base + r) * 132 + c] = yl[r];
            }
        }
        __syncthreads();
        if (base > 0) {
            int total = base * 132;
            for (int idx = tid; idx < total; idx += 512) {
                int r = idx / 132;
                int c = idx % 132;
                float s = sR[r * 132 + c];
#pragma unroll
                for (int m = 0; m < 16; m++)
                    s -= sL[(base + m) * 68 + r] * sR[(base + m) * 132 + c];
                sR[r * 132 + c] = s;
            }
        }
        __syncthreads();
    }

    // store K, k (full CTA, coalesced); sR holds the solution y, K = -y
    {
        float* Kb = g_K + ((size_t)t * B_ + b) * (M_ * N_);
        for (int idx = tid; idx < 64 * 128; idx += 512) {
            int j = idx >> 7, cc = idx & 127;
            Kb[j * 128 + cc] = -sR[j * 132 + cc];
        }
        if (tid < 64) {
            float kv = -sR[tid * 132 + 128];
            g_k[((size_t)t * B_ + b) * M_ + tid] = kv;
            sk[tid] = kv;
        }
    }
    __syncthreads();

    // vn = qx + Qux^T k   (Qux re-read from global; sR was overwritten)
    if (tid < 128) {
        float acc = g_qhat[b * NT_ + tid];
#pragma unroll 8
        for (int m = 0; m < 64; m++) acc += Qub[m * NT_ + tid] * sk[m];
        g_v[b * 128 + tid] = acc;
    }
}

// ---------------- k4: Vn = Qxx + Qux^T @ K ----------------
__global__ __launch_bounds__(256) void k4_Vn(int t) {
    int b = blockIdx.y, bx = blockIdx.x, tid = threadIdx.x;
    int ib = (bx >> 1) * 64, jb = (bx & 1) * 64;
    const float* Qub = g_Qu + b * M_ * NT_;
    const float* Kb = g_K + ((size_t)t * B_ + b) * (M_ * N_);
    __shared__ float As[16][64];
    __shared__ float Bs[16][64];
    int tx = tid & 15, ty = tid >> 4;
    float acc[4][4] = {};

    for (int kb = 0; kb < 4; kb++) {
        int k = kb * 16 + ty;
        *(float4*)&As[ty][tx * 4] = *(const float4*)(Qub + k * NT_ + ib + tx * 4);
        *(float4*)&Bs[ty][tx * 4] = *(const float4*)(Kb + k * 128 + jb + tx * 4);
        __syncthreads();
#pragma unroll
        for (int kk = 0; kk < 16; kk++) {
            float4 a = *(float4*)&As[kk][ty * 4];
            float4 bq = *(float4*)&Bs[kk][tx * 4];
            FMA16(a, bq)
        }
        __syncthreads();
    }
    const float* Qxxb = g_Qxx + b * N_ * N_;
    float* Vb = g_V + b * N_ * N_;
#pragma unroll
    for (int i = 0; i < 4; i++) {
        int r = ib + ty * 4 + i, cc = jb + tx * 4;
        float4 q4 = *(const float4*)(Qxxb + r * N_ + cc);
        *(float4*)(Vb + r * N_ + cc) =
            make_float4(acc[i][0] + q4.x, acc[i][1] + q4.y, acc[i][2] + q4.z, acc[i][3] + q4.w);
    }
}

// ---------------- forward rollout ----------------
__global__ __launch_bounds__(256) void kfwd(const float* __restrict__ A,
                                            const float* __restrict__ Bm,
                                            const float* __restrict__ c1,
                                            const float* __restrict__ xinit,
                                            float* __restrict__ out) {
    int b = blockIdx.x, tid = threadIdx.x;
    int warp = tid >> 5, lane = tid & 31;
    __shared__ float sx[128], su[64], sxn[128];
    if (tid < 128) sx[tid] = xinit[b * 128 + tid];
    __syncthreads();

    for (int t = 0; t < 128; t++) {
        size_t bt = (size_t)b * T_ + t;
        const float* Kb = g_K + ((size_t)t * B_ + b) * (M_ * N_);
        const float* kb = g_k + ((size_t)t * B_ + b) * M_;
        for (int r = warp; r < 64; r += 8) {
            const float* kr = Kb + r * 128;
            float s = kr[lane] * sx[lane] + kr[32 + lane] * sx[32 + lane]
                    + kr[64 + lane] * sx[64 + lane] + kr[96 + lane] * sx[96 + lane];
#pragma unroll
            for (int o = 16; o; o >>= 1) s += __shfl_down_sync(0xffffffffu, s, o);
            if (lane == 0) su[r] = s + kb[r];
        }
        if (tid < 128) out[bt * NT_ + tid] = sx[tid];
        __syncthreads();
        if (tid < 64) out[bt * NT_ + 128 + tid] = su[tid];

        const float* Ab = A + bt * (size_t)(N_ * N_);
        const float* Bb = Bm + bt * (size_t)(N_ * M_);
        for (int r = warp; r < 128; r += 8) {
            const float* ar = Ab + r * 128;
            const float* br = Bb + r * 64;
            float s = ar[lane] * sx[lane] + ar[32 + lane] * sx[32 + lane]
                    + ar[64 + lane] * sx[64 + lane] + ar[96 + lane] * sx[96 + lane]
                    + br[lane] * su[lane] + br[32 + lane] * su[32 + lane];
#pragma unroll
            for (int o = 16; o; o >>= 1) s += __shfl_down_sync(0xffffffffu, s, o);
            if (lane == 0) sxn[r] = s + c1[bt * 128 + r];
        }
        __syncthreads();
        if (tid < 128) sx[tid] = sxn[tid];
        __syncthreads();
    }
}

// ---------------- launch ----------------
extern "C" void kernel_launch(void* const* d_in, const int* in_sizes, int n_in,
                              void* d_out, int out_size) {
    const float *A = 0, *Bm = 0, *c1 = 0, *Q = 0, *p = 0, *xinit = 0;
    for (int i = 0; i < n_in; i++) {
        switch (in_sizes[i]) {
            case 67108864:  A = (const float*)d_in[i]; break;      // 32*128*128*128
            case 33554432:  Bm = (const float*)d_in[i]; break;     // 32*128*128*64
            case 524288:    c1 = (const float*)d_in[i]; break;     // 32*128*128
            case 150994944: Q = (const float*)d_in[i]; break;      // 32*128*192*192
            case 786432:    p = (const float*)d_in[i]; break;      // 32*128*192
            case 4096:      xinit = (const float*)d_in[i]; break;  // 32*128
        }
    }
    float* out = (float*)d_out;

    int k3_smem = SM_TOT * (int)sizeof(float);
    cudaFuncSetAttribute(k3_solve, cudaFuncAttributeMaxDynamicSharedMemorySize, k3_smem);

    kzero<<<(B_ * N_ * N_ + 255) / 256, 256>>>();
    for (int t = T_ - 1; t >= 0; t--) {
        k1_VF<<<dim3(7, B_), 256>>>(A, Bm, c1, t);
        k2_Qhat<<<dim3(8, B_), 256>>>(A, Bm, Q, p, t);
        k3_solve<<<B_, 512, k3_smem>>>(t);
        k4_Vn<<<dim3(4, B_), 256>>>(t);
    }
    kfwd<<<B_, 256>>>(A, Bm, c1, xinit, out);
}

// round 9
// speedup vs baseline: 1.1169x; 1.1169x over previous
#include <cuda_runtime.h>

#define B_ 32
#define T_ 128
#define N_ 128
#define M_ 64
#define NT_ 192

// ---------------- device scratch (no allocations allowed) ----------------
__device__ float g_V[B_ * N_ * N_];
__device__ float g_v[B_ * N_];
__device__ float g_w[B_ * N_];
__device__ float g_VF[B_ * N_ * NT_];
__device__ float g_Qxx[B_ * N_ * N_];
__device__ float g_Qu[B_ * M_ * NT_];   // rows 0..63: cols 0..127 = Qux, 128..191 = Quu
__device__ float g_qhat[B_ * NT_];
__device__ float g_K[(size_t)T_ * B_ * M_ * N_];
__device__ float g_k[T_ * B_ * M_];

#define FMA16(a, bq)                                                                   \
    acc[0][0] += a.x * bq.x; acc[0][1] += a.x * bq.y; acc[0][2] += a.x * bq.z; acc[0][3] += a.x * bq.w; \
    acc[1][0] += a.y * bq.x; acc[1][1] += a.y * bq.y; acc[1][2] += a.y * bq.z; acc[1][3] += a.y * bq.w; \
    acc[2][0] += a.z * bq.x; acc[2][1] += a.z * bq.y; acc[2][2] += a.z * bq.z; acc[2][3] += a.z * bq.w; \
    acc[3][0] += a.w * bq.x; acc[3][1] += a.w * bq.y; acc[3][2] += a.w * bq.z; acc[3][3] += a.w * bq.w;

// ---------------- init ----------------
__global__ void kzero() {
    int idx = blockIdx.x * 256 + threadIdx.x;
    if (idx < B_ * N_ * N_) g_V[idx] = 0.0f;
    if (idx < B_ * N_) g_v[idx] = 0.0f;
}

// ---------------- k1: VF = V @ [A|B]  (uses V symmetry), w = V c + v ----------------
__global__ __launch_bounds__(256) void k1_VF(const float* __restrict__ A,
                                             const float* __restrict__ Bm,
                                             const float* __restrict__ c1, int t) {
    int b = blockIdx.y;
    int bx = blockIdx.x;
    int tid = threadIdx.x;
    const float* Vb = g_V + b * N_ * N_;
    size_t bt = (size_t)b * T_ + t;

    if (bx == 6) {  // w = V c + v  (V symmetric -> coalesced column read)
        __shared__ float cs[128];
        if (tid < 128) cs[tid] = c1[bt * 128 + tid];
        __syncthreads();
        if (tid < 128) {
            float acc = g_v[b * 128 + tid];
#pragma unroll 8
            for (int m = 0; m < 128; m++) acc += Vb[m * 128 + tid] * cs[m];
            g_w[b * 128 + tid] = acc;
        }
        return;
    }

    int tr = bx / 3, tc = bx % 3;
    int rb = tr * 64, cb = tc * 64;
    const float* Fsrc; int ldF, coff;
    if (cb < 128) { Fsrc = A + bt * (size_t)(N_ * N_); ldF = 128; coff = cb; }
    else          { Fsrc = Bm + bt * (size_t)(N_ * M_); ldF = 64;  coff = 0;  }

    __shared__ float As[16][64];
    __shared__ float Bs[16][64];
    int tx = tid & 15, ty = tid >> 4;
    float acc[4][4] = {};

    for (int kb = 0; kb < 8; kb++) {
        int k = kb * 16 + ty;
        // V symmetric: V[row][k] == V[k][row]
        *(float4*)&As[ty][tx * 4] = *(const float4*)(Vb + k * 128 + rb + tx * 4);
        *(float4*)&Bs[ty][tx * 4] = *(const float4*)(Fsrc + (size_t)k * ldF + coff + tx * 4);
        __syncthreads();
#pragma unroll
        for (int kk = 0; kk < 16; kk++) {
            float4 a = *(float4*)&As[kk][ty * 4];
            float4 bq = *(float4*)&Bs[kk][tx * 4];
            FMA16(a, bq)
        }
        __syncthreads();
    }
    float* outp = g_VF + b * N_ * NT_;
#pragma unroll
    for (int i = 0; i < 4; i++) {
        *(float4*)(outp + (rb + ty * 4 + i) * NT_ + cb + tx * 4) =
            make_float4(acc[i][0], acc[i][1], acc[i][2], acc[i][3]);
    }
}

// ---------------- k2: Qxx = Qxx + A^T VF ; [Qux|Quu] = Q_u + B^T VF ; qhat ----------------
__global__ __launch_bounds__(256) void k2_Qhat(const float* __restrict__ A,
                                               const float* __restrict__ Bm,
                                               const float* __restrict__ Q,
                                               const float* __restrict__ p, int t) {
    int b = blockIdx.y, bx = blockIdx.x, tid = threadIdx.x;
    size_t bt = (size_t)b * T_ + t;

    if (bx == 7) {  // qhat = p + F^T w
        __shared__ float ws[128];
        if (tid < 128) ws[tid] = g_w[b * 128 + tid];
        __syncthreads();
        if (tid < 192) {
            float acc = p[bt * NT_ + tid];
            if (tid < 128) {
                const float* Ab = A + bt * (size_t)(N_ * N_);
#pragma unroll 4
                for (int n = 0; n < 128; n++) acc += Ab[n * 128 + tid] * ws[n];
            } else {
                const float* Bb = Bm + bt * (size_t)(N_ * M_);
                int j = tid - 128;
#pragma unroll 4
                for (int n = 0; n < 128; n++) acc += Bb[n * 64 + j] * ws[n];
            }
            g_qhat[b * NT_ + tid] = acc;
        }
        return;
    }

    bool isQxx = bx < 4;
    int ib, jb; const float* Asrc; int lda, aoff;
    if (isQxx) { ib = (bx >> 1) * 64; jb = (bx & 1) * 64; Asrc = A + bt * (size_t)(N_ * N_); lda = 128; aoff = ib; }
    else       { ib = 0; jb = (bx - 4) * 64; Asrc = Bm + bt * (size_t)(N_ * M_); lda = 64; aoff = 0; }

    __shared__ float As[16][64];
    __shared__ float Bs[16][64];
    int tx = tid & 15, ty = tid >> 4;
    const float* VFb = g_VF + b * N_ * NT_;
    float acc[4][4] = {};

    for (int kb = 0; kb < 8; kb++) {
        int k = kb * 16 + ty;
        *(float4*)&As[ty][tx * 4] = *(const float4*)(Asrc + (size_t)k * lda + aoff + tx * 4);
        *(float4*)&Bs[ty][tx * 4] = *(const float4*)(VFb + k * NT_ + jb + tx * 4);
        __syncthreads();
#pragma unroll
        for (int kk = 0; kk < 16; kk++) {
            float4 a = *(float4*)&As[kk][ty * 4];
            float4 bq = *(float4*)&Bs[kk][tx * 4];
            FMA16(a, bq)
        }
        __syncthreads();
    }

    const float* Qb = Q + bt * (size_t)(NT_ * NT_);
    if (isQxx) {
        float* outp = g_Qxx + b * N_ * N_;
#pragma unroll
        for (int i = 0; i < 4; i++) {
            int r = ib + ty * 4 + i, cc = jb + tx * 4;
            float4 q4 = *(const float4*)(Qb + (size_t)r * NT_ + cc);
            *(float4*)(outp + r * N_ + cc) =
                make_float4(acc[i][0] + q4.x, acc[i][1] + q4.y, acc[i][2] + q4.z, acc[i][3] + q4.w);
        }
    } else {
        float* outp = g_Qu + b * M_ * NT_;
#pragma unroll
        for (int i = 0; i < 4; i++) {
            int r = ty * 4 + i, cc = jb + tx * 4;
            float4 q4 = *(const float4*)(Qb + (size_t)(128 + r) * NT_ + cc);
            *(float4*)(outp + r * NT_ + cc) =
                make_float4(acc[i][0] + q4.x, acc[i][1] + q4.y, acc[i][2] + q4.z, acc[i][3] + q4.w);
        }
    }
}

// ---------------- k3: Cholesky + 129-RHS solve + fused Vn -> K, k, vn, Vn ----------------
// Dynamic smem layout:
//   sL   [64*68]  : L in lower triangle (L^T read via broadcast)
//   sR   [64*132] : RHS (cols 0..127 = Qux, col 128 = qu, 129..131 junk); solved IN PLACE
//   sPT  [16*66]  : transposed panel for Cholesky trailing update
//   sInvD[64], sk[64]
#define SM_L   0
#define SM_R   (64 * 68)
#define SM_PT  (SM_R + 64 * 132)
#define SM_ID  (SM_PT + 16 * 66)
#define SM_K   (SM_ID + 64)
#define SM_TOT (SM_K + 64)   // floats

__global__ __launch_bounds__(512) void k3_solve(int t) {
    extern __shared__ __align__(16) float sm[];
    float* sL = sm + SM_L;
    float* sR = sm + SM_R;
    float* sPT = sm + SM_PT;
    float* sInvD = sm + SM_ID;
    float* sk = sm + SM_K;

    int b = blockIdx.x, tid = threadIdx.x;
    const float* Qub = g_Qu + b * M_ * NT_;

    // stage Quu into sL and RHS into sR (float4, coalesced)
    for (int idx = tid; idx < 64 * 16; idx += 512) {
        int i = idx >> 4, j4 = idx & 15;
        *(float4*)&sL[i * 68 + j4 * 4] = *(const float4*)(Qub + i * NT_ + 128 + j4 * 4);
    }
    for (int idx = tid; idx < 64 * 32; idx += 512) {
        int i = idx >> 5, c4 = idx & 31;
        *(float4*)&sR[i * 132 + c4 * 4] = *(const float4*)(Qub + i * NT_ + c4 * 4);
    }
    if (tid < 64) sR[tid * 132 + 128] = g_qhat[b * NT_ + 128 + tid];
    __syncthreads();

    // ---- blocked lower Cholesky, 16-wide panels ----
    for (int kb = 0; kb < 64; kb += 16) {
        // 1) factor 16x16 diagonal block in registers via shfl (warp 0)
        if (tid < 32) {
            int l = tid & 15;
            int row = kb + l;
            float a[16];
#pragma unroll
            for (int i = 0; i < 16; i++) a[i] = sL[row * 68 + kb + i];
#pragma unroll
            for (int i = 0; i < 16; i++) {
                float aii = __shfl_sync(0xffffffffu, a[i], i);
                float dinv = rsqrtf(aii);
                a[i] *= dinv;
                if (tid == i) sInvD[kb + i] = dinv;
#pragma unroll
                for (int c = i + 1; c < 16; c++) {
                    float lci = __shfl_sync(0xffffffffu, a[i], c);
                    a[c] -= a[i] * lci;
                }
            }
            if (tid < 16) {
#pragma unroll
                for (int i = 0; i < 16; i++)
                    if (i <= l) sL[row * 68 + kb + i] = a[i];
            }
        }
        __syncthreads();

        int rem = 48 - kb;  // panel rows below the diagonal block
        if (rem > 0) {
            // 2) panel solve: one thread per row r = kb+16..63
            if (tid < rem) {
                int r = kb + 16 + tid;
                float a[16];
#pragma unroll
                for (int i = 0; i < 16; i++) a[i] = sL[r * 68 + kb + i];
#pragma unroll
                for (int i = 0; i < 16; i++) {
                    float s = a[i];
#pragma unroll
                    for (int m = 0; m < i; m++) s -= a[m] * sL[(kb + i) * 68 + kb + m];
                    a[i] = s * sInvD[kb + i];
                }
#pragma unroll
                for (int i = 0; i < 16; i++) {
                    sL[r * 68 + kb + i] = a[i];
                    sPT[i * 66 + r] = a[i];   // transposed copy for the update
                }
            }
            __syncthreads();

            // 3) trailing rank-16 update (reads via sPT: conflict-free)
            int total = rem * 64;
            for (int idx = tid; idx < total; idx += 512) {
                int jr = kb + 16 + (idx >> 6);
                int c = idx & 63;
                if (c >= kb + 16 && c <= jr) {
                    float s = sL[jr * 68 + c];
#pragma unroll
                    for (int m = 0; m < 16; m++)
                        s -= sPT[m * 66 + jr] * sPT[m * 66 + c];
                    sL[jr * 68 + c] = s;
                }
            }
            __syncthreads();
        }
    }

    // ---- forward substitution: L y = rhs (in place in sR) ----
    for (int jb = 0; jb < 4; jb++) {
        int base = jb * 16;
        if (tid < 132) {
            int c = tid;
            float yl[16];
#pragma unroll
            for (int r = 0; r < 16; r++) yl[r] = sR[(base + r) * 132 + c];
#pragma unroll
            for (int r = 0; r < 16; r++) {
                float s = yl[r];
#pragma unroll
                for (int m = 0; m < r; m++) s -= sL[(base + r) * 68 + base + m] * yl[m];
                yl[r] = s * sInvD[base + r];
                sR[(base + r) * 132 + c] = yl[r];
            }
        }
        __syncthreads();
        int ng = 3 - jb;  // 16-row groups below
        if (ng > 0) {
            int slot = tid;
            if (slot < 132 * ng) {
                int c = slot % 132;
                int g = slot / 132;
                int r0 = base + 16 + g * 16;
                float yv[16];
#pragma unroll
                for (int m = 0; m < 16; m++) yv[m] = sR[(base + m) * 132 + c];
#pragma unroll
                for (int r = 0; r < 16; r++) {
                    float s = sR[(r0 + r) * 132 + c];
#pragma unroll
                    for (int m = 0; m < 16; m++)
                        s -= sL[(r0 + r) * 68 + base + m] * yv[m];
                    sR[(r0 + r) * 132 + c] = s;
                }
            }
        }
        __syncthreads();
    }

    // ---- backward substitution: L^T x = y (L read transposed, broadcast) ----
    for (int jb = 3; jb >= 0; jb--) {
        int base = jb * 16;
        if (tid < 132) {
            int c = tid;
            float yl[16];
#pragma unroll
            for (int r = 0; r < 16; r++) yl[r] = sR[(base + r) * 132 + c];
#pragma unroll
            for (int r = 15; r >= 0; r--) {
                float s = yl[r];
#pragma unroll
                for (int m = r + 1; m < 16; m++) s -= sL[(base + m) * 68 + base + r] * yl[m];
                yl[r] = s * sInvD[base + r];
                sR[(base + r) * 132 + c] = yl[r];
            }
        }
        __syncthreads();
        if (jb > 0) {
            int slot = tid;
            if (slot < 132 * jb) {
                int c = slot % 132;
                int g = slot / 132;
                int r0 = g * 16;
                float yv[16];
#pragma unroll
                for (int m = 0; m < 16; m++) yv[m] = sR[(base + m) * 132 + c];
#pragma unroll
                for (int r = 0; r < 16; r++) {
                    float s = sR[(r0 + r) * 132 + c];
#pragma unroll
                    for (int m = 0; m < 16; m++)
                        s -= sL[(base + m) * 68 + (r0 + r)] * yv[m];
                    sR[(r0 + r) * 132 + c] = s;
                }
            }
        }
        __syncthreads();
    }

    // ---- store K, k (coalesced); sR holds the solution y, K = -y ----
    {
        float* Kb = g_K + ((size_t)t * B_ + b) * (M_ * N_);
        for (int idx = tid; idx < 64 * 128; idx += 512) {
            int j = idx >> 7, cc = idx & 127;
            Kb[j * 128 + cc] = -sR[j * 132 + cc];
        }
        if (tid < 64) {
            float kv = -sR[tid * 132 + 128];
            g_k[((size_t)t * B_ + b) * M_ + tid] = kv;
            sk[tid] = kv;
        }
    }
    __syncthreads();

    // ---- vn = qx + Qux^T k (Qux re-read from global; sR was overwritten) ----
    if (tid < 128) {
        float acc = g_qhat[b * NT_ + tid];
#pragma unroll 8
        for (int m = 0; m < 64; m++) acc += Qub[m * NT_ + tid] * sk[m];
        g_v[b * 128 + tid] = acc;
    }

    // ---- fused Vn = Qxx - Qux^T @ y  (y = sR; Qux broadcast from global/L1) ----
    {
        int tx = tid & 31;        // j4-group: cols j = tx*4 .. tx*4+3
        int ty = tid >> 5;        // row group: rows i = ty*8 .. ty*8+7
        float acc8[8][4] = {};
#pragma unroll 4
        for (int m = 0; m < 64; m++) {
            float4 yv = *(const float4*)&sR[m * 132 + tx * 4];
            const float* qrow = Qub + m * NT_ + ty * 8;
#pragma unroll
            for (int rr = 0; rr < 8; rr++) {
                float qv = qrow[rr];
                acc8[rr][0] += qv * yv.x;
                acc8[rr][1] += qv * yv.y;
                acc8[rr][2] += qv * yv.z;
                acc8[rr][3] += qv * yv.w;
            }
        }
        const float* Qxxb = g_Qxx + b * N_ * N_;
        float* Vb = g_V + b * N_ * N_;
#pragma unroll
        for (int rr = 0; rr < 8; rr++) {
            int i = ty * 8 + rr;
            float4 q4 = *(const float4*)(Qxxb + i * N_ + tx * 4);
            *(float4*)(Vb + i * N_ + tx * 4) =
                make_float4(q4.x - acc8[rr][0], q4.y - acc8[rr][1],
                            q4.z - acc8[rr][2], q4.w - acc8[rr][3]);
        }
    }
}

// ---------------- forward rollout ----------------
__global__ __launch_bounds__(256) void kfwd(const float* __restrict__ A,
                                            const float* __restrict__ Bm,
                                            const float* __restrict__ c1,
                                            const float* __restrict__ xinit,
                                            float* __restrict__ out) {
    int b = blockIdx.x, tid = threadIdx.x;
    int warp = tid >> 5, lane = tid & 31;
    __shared__ float sx[128], su[64], sxn[128];
    if (tid < 128) sx[tid] = xinit[b * 128 + tid];
    __syncthreads();

    for (int t = 0; t < 128; t++) {
        size_t bt = (size_t)b * T_ + t;
        const float* Kb = g_K + ((size_t)t * B_ + b) * (M_ * N_);
        const float* kb = g_k + ((size_t)t * B_ + b) * M_;
        for (int r = warp; r < 64; r += 8) {
            const float* kr = Kb + r * 128;
            float s = kr[lane] * sx[lane] + kr[32 + lane] * sx[32 + lane]
                    + kr[64 + lane] * sx[64 + lane] + kr[96 + lane] * sx[96 + lane];
#pragma unroll
            for (int o = 16; o; o >>= 1) s += __shfl_down_sync(0xffffffffu, s, o);
            if (lane == 0) su[r] = s + kb[r];
        }
        if (tid < 128) out[bt * NT_ + tid] = sx[tid];
        __syncthreads();
        if (tid < 64) out[bt * NT_ + 128 + tid] = su[tid];

        const float* Ab = A + bt * (size_t)(N_ * N_);
        const float* Bb = Bm + bt * (size_t)(N_ * M_);
        for (int r = warp; r < 128; r += 8) {
            const float* ar = Ab + r * 128;
            const float* br = Bb + r * 64;
            float s = ar[lane] * sx[lane] + ar[32 + lane] * sx[32 + lane]
                    + ar[64 + lane] * sx[64 + lane] + ar[96 + lane] * sx[96 + lane]
                    + br[lane] * su[lane] + br[32 + lane] * su[32 + lane];
#pragma unroll
            for (int o = 16; o; o >>= 1) s += __shfl_down_sync(0xffffffffu, s, o);
            if (lane == 0) sxn[r] = s + c1[bt * 128 + r];
        }
        __syncthreads();
        if (tid < 128) sx[tid] = sxn[tid];
        __syncthreads();
    }
}

// ---------------- launch ----------------
extern "C" void kernel_launch(void* const* d_in, const int* in_sizes, int n_in,
                              void* d_out, int out_size) {
    const float *A = 0, *Bm = 0, *c1 = 0, *Q = 0, *p = 0, *xinit = 0;
    for (int i = 0; i < n_in; i++) {
        switch (in_sizes[i]) {
            case 67108864:  A = (const float*)d_in[i]; break;      // 32*128*128*128
            case 33554432:  Bm = (const float*)d_in[i]; break;     // 32*128*128*64
            case 524288:    c1 = (const float*)d_in[i]; break;     // 32*128*128
            case 150994944: Q = (const float*)d_in[i]; break;      // 32*128*192*192
            case 786432:    p = (const float*)d_in[i]; break;      // 32*128*192
            case 4096:      xinit = (const float*)d_in[i]; break;  // 32*128
        }
    }
    float* out = (float*)d_out;

    int k3_smem = SM_TOT * (int)sizeof(float);
    cudaFuncSetAttribute(k3_solve, cudaFuncAttributeMaxDynamicSharedMemorySize, k3_smem);

    kzero<<<(B_ * N_ * N_ + 255) / 256, 256>>>();
    for (int t = T_ - 1; t >= 0; t--) {
        k1_VF<<<dim3(7, B_), 256>>>(A, Bm, c1, t);
        k2_Qhat<<<dim3(8, B_), 256>>>(A, Bm, Q, p, t);
        k3_solve<<<B_, 512, k3_smem>>>(t);
    }
    kfwd<<<B_, 256>>>(A, Bm, c1, xinit, out);
}

// round 10
// speedup vs baseline: 1.1941x; 1.0691x over previous
#include <cuda_runtime.h>

#define B_ 32
#define T_ 128
#define N_ 128
#define M_ 64
#define NT_ 192

// ---------------- device scratch (no allocations allowed) ----------------
__device__ float g_V[B_ * N_ * N_];
__device__ float g_v[B_ * N_];
__device__ float g_w[B_ * N_];
__device__ float g_VF[B_ * N_ * NT_];
__device__ float g_Qxx[B_ * N_ * N_];
__device__ float g_Qu[B_ * M_ * NT_];   // rows 0..63: cols 0..127 = Qux, 128..191 = Quu
__device__ float g_qhat[B_ * NT_];
__device__ float g_L[B_ * M_ * M_];     // factored L (lower), per batch
__device__ float g_invD[B_ * M_];
__device__ float g_K[(size_t)T_ * B_ * M_ * N_];
__device__ float g_k[T_ * B_ * M_];

#define FMA16(a, bq)                                                                   \
    acc[0][0] += a.x * bq.x; acc[0][1] += a.x * bq.y; acc[0][2] += a.x * bq.z; acc[0][3] += a.x * bq.w; \
    acc[1][0] += a.y * bq.x; acc[1][1] += a.y * bq.y; acc[1][2] += a.y * bq.z; acc[1][3] += a.y * bq.w; \
    acc[2][0] += a.z * bq.x; acc[2][1] += a.z * bq.y; acc[2][2] += a.z * bq.z; acc[2][3] += a.z * bq.w; \
    acc[3][0] += a.w * bq.x; acc[3][1] += a.w * bq.y; acc[3][2] += a.w * bq.z; acc[3][3] += a.w * bq.w;

// ---------------- init ----------------
__global__ void kzero() {
    int idx = blockIdx.x * 256 + threadIdx.x;
    if (idx < B_ * N_ * N_) g_V[idx] = 0.0f;
    if (idx < B_ * N_) g_v[idx] = 0.0f;
}

// ---------------- k1: VF = V @ [A|B]  (uses V symmetry), w = V c + v ----------------
__global__ __launch_bounds__(256) void k1_VF(const float* __restrict__ A,
                                             const float* __restrict__ Bm,
                                             const float* __restrict__ c1, int t) {
    int b = blockIdx.y;
    int bx = blockIdx.x;
    int tid = threadIdx.x;
    const float* Vb = g_V + b * N_ * N_;
    size_t bt = (size_t)b * T_ + t;

    if (bx == 6) {  // w = V c + v  (V symmetric -> coalesced column read)
        __shared__ float cs[128];
        if (tid < 128) cs[tid] = c1[bt * 128 + tid];
        __syncthreads();
        if (tid < 128) {
            float acc = g_v[b * 128 + tid];
#pragma unroll 8
            for (int m = 0; m < 128; m++) acc += Vb[m * 128 + tid] * cs[m];
            g_w[b * 128 + tid] = acc;
        }
        return;
    }

    int tr = bx / 3, tc = bx % 3;
    int rb = tr * 64, cb = tc * 64;
    const float* Fsrc; int ldF, coff;
    if (cb < 128) { Fsrc = A + bt * (size_t)(N_ * N_); ldF = 128; coff = cb; }
    else          { Fsrc = Bm + bt * (size_t)(N_ * M_); ldF = 64;  coff = 0;  }

    __shared__ float As[16][64];
    __shared__ float Bs[16][64];
    int tx = tid & 15, ty = tid >> 4;
    float acc[4][4] = {};

    for (int kb = 0; kb < 8; kb++) {
        int k = kb * 16 + ty;
        // V symmetric: V[row][k] == V[k][row]
        *(float4*)&As[ty][tx * 4] = *(const float4*)(Vb + k * 128 + rb + tx * 4);
        *(float4*)&Bs[ty][tx * 4] = *(const float4*)(Fsrc + (size_t)k * ldF + coff + tx * 4);
        __syncthreads();
#pragma unroll
        for (int kk = 0; kk < 16; kk++) {
            float4 a = *(float4*)&As[kk][ty * 4];
            float4 bq = *(float4*)&Bs[kk][tx * 4];
            FMA16(a, bq)
        }
        __syncthreads();
    }
    float* outp = g_VF + b * N_ * NT_;
#pragma unroll
    for (int i = 0; i < 4; i++) {
        *(float4*)(outp + (rb + ty * 4 + i) * NT_ + cb + tx * 4) =
            make_float4(acc[i][0], acc[i][1], acc[i][2], acc[i][3]);
    }
}

// ---------------- k2: Qxx = Qxx + A^T VF ; [Qux|Quu] = Q_u + B^T VF ; qhat ----------------
__global__ __launch_bounds__(256) void k2_Qhat(const float* __restrict__ A,
                                               const float* __restrict__ Bm,
                                               const float* __restrict__ Q,
                                               const float* __restrict__ p, int t) {
    int b = blockIdx.y, bx = blockIdx.x, tid = threadIdx.x;
    size_t bt = (size_t)b * T_ + t;

    if (bx == 7) {  // qhat = p + F^T w
        __shared__ float ws[128];
        if (tid < 128) ws[tid] = g_w[b * 128 + tid];
        __syncthreads();
        if (tid < 192) {
            float acc = p[bt * NT_ + tid];
            if (tid < 128) {
                const float* Ab = A + bt * (size_t)(N_ * N_);
#pragma unroll 4
                for (int n = 0; n < 128; n++) acc += Ab[n * 128 + tid] * ws[n];
            } else {
                const float* Bb = Bm + bt * (size_t)(N_ * M_);
                int j = tid - 128;
#pragma unroll 4
                for (int n = 0; n < 128; n++) acc += Bb[n * 64 + j] * ws[n];
            }
            g_qhat[b * NT_ + tid] = acc;
        }
        return;
    }

    bool isQxx = bx < 4;
    int ib, jb; const float* Asrc; int lda, aoff;
    if (isQxx) { ib = (bx >> 1) * 64; jb = (bx & 1) * 64; Asrc = A + bt * (size_t)(N_ * N_); lda = 128; aoff = ib; }
    else       { ib = 0; jb = (bx - 4) * 64; Asrc = Bm + bt * (size_t)(N_ * M_); lda = 64; aoff = 0; }

    __shared__ float As[16][64];
    __shared__ float Bs[16][64];
    int tx = tid & 15, ty = tid >> 4;
    const float* VFb = g_VF + b * N_ * NT_;
    float acc[4][4] = {};

    for (int kb = 0; kb < 8; kb++) {
        int k = kb * 16 + ty;
        *(float4*)&As[ty][tx * 4] = *(const float4*)(Asrc + (size_t)k * lda + aoff + tx * 4);
        *(float4*)&Bs[ty][tx * 4] = *(const float4*)(VFb + k * NT_ + jb + tx * 4);
        __syncthreads();
#pragma unroll
        for (int kk = 0; kk < 16; kk++) {
            float4 a = *(float4*)&As[kk][ty * 4];
            float4 bq = *(float4*)&Bs[kk][tx * 4];
            FMA16(a, bq)
        }
        __syncthreads();
    }

    const float* Qb = Q + bt * (size_t)(NT_ * NT_);
    if (isQxx) {
        float* outp = g_Qxx + b * N_ * N_;
#pragma unroll
        for (int i = 0; i < 4; i++) {
            int r = ib + ty * 4 + i, cc = jb + tx * 4;
            float4 q4 = *(const float4*)(Qb + (size_t)r * NT_ + cc);
            *(float4*)(outp + r * N_ + cc) =
                make_float4(acc[i][0] + q4.x, acc[i][1] + q4.y, acc[i][2] + q4.z, acc[i][3] + q4.w);
        }
    } else {
        float* outp = g_Qu + b * M_ * NT_;
#pragma unroll
        for (int i = 0; i < 4; i++) {
            int r = ty * 4 + i, cc = jb + tx * 4;
            float4 q4 = *(const float4*)(Qb + (size_t)(128 + r) * NT_ + cc);
            *(float4*)(outp + r * NT_ + cc) =
                make_float4(acc[i][0] + q4.x, acc[i][1] + q4.y, acc[i][2] + q4.z, acc[i][3] + q4.w);
        }
    }
}

// ---------------- k3a: blocked Cholesky(Quu) -> g_L, g_invD ----------------
__global__ __launch_bounds__(256) void k3a_chol() {
    __shared__ __align__(16) float sL[64 * 68];
    __shared__ float sPT[16 * 66];
    __shared__ float sInvD[64];
    int b = blockIdx.x, tid = threadIdx.x;
    const float* Qub = g_Qu + b * M_ * NT_;

    for (int idx = tid; idx < 64 * 16; idx += 256) {
        int i = idx >> 4, j4 = idx & 15;
        *(float4*)&sL[i * 68 + j4 * 4] = *(const float4*)(Qub + i * NT_ + 128 + j4 * 4);
    }
    __syncthreads();

    for (int kb = 0; kb < 64; kb += 16) {
        // 1) factor 16x16 diagonal block in registers via shfl (warp 0)
        if (tid < 32) {
            int l = tid & 15;
            int row = kb + l;
            float a[16];
#pragma unroll
            for (int i = 0; i < 16; i++) a[i] = sL[row * 68 + kb + i];
#pragma unroll
            for (int i = 0; i < 16; i++) {
                float aii = __shfl_sync(0xffffffffu, a[i], i);
                float dinv = rsqrtf(aii);
                a[i] *= dinv;
                if (tid == i) sInvD[kb + i] = dinv;
#pragma unroll
                for (int c = i + 1; c < 16; c++) {
                    float lci = __shfl_sync(0xffffffffu, a[i], c);
                    a[c] -= a[i] * lci;
                }
            }
            if (tid < 16) {
#pragma unroll
                for (int i = 0; i < 16; i++)
                    if (i <= l) sL[row * 68 + kb + i] = a[i];
            }
        }
        __syncthreads();

        int rem = 48 - kb;
        if (rem > 0) {
            // 2) panel solve
            if (tid < rem) {
                int r = kb + 16 + tid;
                float a[16];
#pragma unroll
                for (int i = 0; i < 16; i++) a[i] = sL[r * 68 + kb + i];
#pragma unroll
                for (int i = 0; i < 16; i++) {
                    float s = a[i];
#pragma unroll
                    for (int m = 0; m < i; m++) s -= a[m] * sL[(kb + i) * 68 + kb + m];
                    a[i] = s * sInvD[kb + i];
                }
#pragma unroll
                for (int i = 0; i < 16; i++) {
                    sL[r * 68 + kb + i] = a[i];
                    sPT[i * 66 + r] = a[i];
                }
            }
            __syncthreads();

            // 3) trailing rank-16 update
            int total = rem * 64;
            for (int idx = tid; idx < total; idx += 256) {
                int jr = kb + 16 + (idx >> 6);
                int c = idx & 63;
                if (c >= kb + 16 && c <= jr) {
                    float s = sL[jr * 68 + c];
#pragma unroll
                    for (int m = 0; m < 16; m++)
                        s -= sPT[m * 66 + jr] * sPT[m * 66 + c];
                    sL[jr * 68 + c] = s;
                }
            }
            __syncthreads();
        }
    }

    // write L (full 64x64, junk upper included) + invD
    float* Lb = g_L + b * M_ * M_;
    for (int idx = tid; idx < 64 * 16; idx += 256) {
        int i = idx >> 4, j4 = idx & 15;
        *(float4*)(Lb + i * 64 + j4 * 4) = *(const float4*)&sL[i * 68 + j4 * 4];
    }
    if (tid < 64) g_invD[b * 64 + tid] = sInvD[tid];
}

// ---------------- k3b: per-column-group solve + K/k + Vn slice + vn ----------------
// grid (4, B_): CTA cg handles Qux columns [cg*32, cg*32+32); cg==0 also qu column.
__global__ __launch_bounds__(256) void k3b_solve(int t) {
    __shared__ __align__(16) float sL[64 * 68];
    __shared__ __align__(16) float sRb[64 * 36];
    __shared__ float sInvD[64];
    __shared__ float sk[64];
    int b = blockIdx.y, cg = blockIdx.x, tid = threadIdx.x;
    int col0 = cg * 32;
    int ncols = (cg == 0) ? 33 : 32;   // local col 32 = qu (cg 0 only)
    const float* Qub = g_Qu + b * M_ * NT_;
    const float* Lb = g_L + b * M_ * M_;

    // stage L + invD
    for (int idx = tid; idx < 64 * 16; idx += 256) {
        int i = idx >> 4, j4 = idx & 15;
        *(float4*)&sL[i * 68 + j4 * 4] = *(const float4*)(Lb + i * 64 + j4 * 4);
    }
    if (tid < 64) sInvD[tid] = g_invD[b * 64 + tid];
    // stage RHS slice
    for (int idx = tid; idx < 64 * 8; idx += 256) {
        int i = idx >> 3, c4 = idx & 7;
        *(float4*)&sRb[i * 36 + c4 * 4] = *(const float4*)(Qub + i * NT_ + col0 + c4 * 4);
    }
    if (cg == 0 && tid < 64) sRb[tid * 36 + 32] = g_qhat[b * NT_ + 128 + tid];
    __syncthreads();

    // ---- forward substitution: L y = rhs ----
    for (int jb = 0; jb < 4; jb++) {
        int base = jb * 16;
        if (tid < ncols) {
            int c = tid;
            float yl[16];
#pragma unroll
            for (int r = 0; r < 16; r++) yl[r] = sRb[(base + r) * 36 + c];
#pragma unroll
            for (int r = 0; r < 16; r++) {
                float s = yl[r];
#pragma unroll
                for (int m = 0; m < r; m++) s -= sL[(base + r) * 68 + base + m] * yl[m];
                yl[r] = s * sInvD[base + r];
                sRb[(base + r) * 36 + c] = yl[r];
            }
        }
        __syncthreads();
        int ng = 3 - jb;
        if (ng > 0 && tid < ncols * ng) {
            int c = tid % ncols;
            int g = tid / ncols;
            int r0 = base + 16 + g * 16;
            float yv[16];
#pragma unroll
            for (int m = 0; m < 16; m++) yv[m] = sRb[(base + m) * 36 + c];
#pragma unroll
            for (int r = 0; r < 16; r++) {
                float s = sRb[(r0 + r) * 36 + c];
#pragma unroll
                for (int m = 0; m < 16; m++)
                    s -= sL[(r0 + r) * 68 + base + m] * yv[m];
                sRb[(r0 + r) * 36 + c] = s;
            }
        }
        __syncthreads();
    }

    // ---- backward substitution: L^T x = y (L read transposed, broadcast) ----
    for (int jb = 3; jb >= 0; jb--) {
        int base = jb * 16;
        if (tid < ncols) {
            int c = tid;
            float yl[16];
#pragma unroll
            for (int r = 0; r < 16; r++) yl[r] = sRb[(base + r) * 36 + c];
#pragma unroll
            for (int r = 15; r >= 0; r--) {
                float s = yl[r];
#pragma unroll
                for (int m = r + 1; m < 16; m++) s -= sL[(base + m) * 68 + base + r] * yl[m];
                yl[r] = s * sInvD[base + r];
                sRb[(base + r) * 36 + c] = yl[r];
            }
        }
        __syncthreads();
        if (jb > 0 && tid < ncols * jb) {
            int c = tid % ncols;
            int g = tid / ncols;
            int r0 = g * 16;
            float yv[16];
#pragma unroll
            for (int m = 0; m < 16; m++) yv[m] = sRb[(base + m) * 36 + c];
#pragma unroll
            for (int r = 0; r < 16; r++) {
                float s = sRb[(r0 + r) * 36 + c];
#pragma unroll
                for (int m = 0; m < 16; m++)
                    s -= sL[(base + m) * 68 + (r0 + r)] * yv[m];
                sRb[(r0 + r) * 36 + c] = s;
            }
        }
        __syncthreads();
    }

    // ---- store K slice; cg 0 stores k, computes vn ----
    {
        float* Kb = g_K + ((size_t)t * B_ + b) * (M_ * N_);
        for (int idx = tid; idx < 64 * 32; idx += 256) {
            int j = idx >> 5, cc = idx & 31;
            Kb[j * 128 + col0 + cc] = -sRb[j * 36 + cc];
        }
        if (cg == 0 && tid < 64) {
            float kv = -sRb[tid * 36 + 32];
            g_k[((size_t)t * B_ + b) * M_ + tid] = kv;
            sk[tid] = kv;
        }
    }
    __syncthreads();

    if (cg == 0 && tid < 128) {
        float acc = g_qhat[b * NT_ + tid];
#pragma unroll 8
        for (int m = 0; m < 64; m++) acc += Qub[m * NT_ + tid] * sk[m];
        g_v[b * 128 + tid] = acc;
    }

    // ---- Vn slice: Vn[:, col0..col0+31] = Qxx[:, cols] - Qux^T @ y(slice) ----
    {
        int tx = tid & 7;         // col group: cols col0 + tx*4 .. +3
        int ty = tid >> 3;        // row group: rows ty*4 .. +3
        float acc[4][4] = {};
#pragma unroll 4
        for (int m = 0; m < 64; m++) {
            float4 yv = *(const float4*)&sRb[m * 36 + tx * 4];
            const float* qrow = Qub + m * NT_ + ty * 4;
#pragma unroll
            for (int rr = 0; rr < 4; rr++) {
                float qv = qrow[rr];
                acc[rr][0] += qv * yv.x;
                acc[rr][1] += qv * yv.y;
                acc[rr][2] += qv * yv.z;
                acc[rr][3] += qv * yv.w;
            }
        }
        const float* Qxxb = g_Qxx + b * N_ * N_;
        float* Vb = g_V + b * N_ * N_;
#pragma unroll
        for (int rr = 0; rr < 4; rr++) {
            int i = ty * 4 + rr;
            float4 q4 = *(const float4*)(Qxxb + i * N_ + col0 + tx * 4);
            *(float4*)(Vb + i * N_ + col0 + tx * 4) =
                make_float4(q4.x - acc[rr][0], q4.y - acc[rr][1],
                            q4.z - acc[rr][2], q4.w - acc[rr][3]);
        }
    }
}

// ---------------- forward rollout ----------------
__global__ __launch_bounds__(256) void kfwd(const float* __restrict__ A,
                                            const float* __restrict__ Bm,
                                            const float* __restrict__ c1,
                                            const float* __restrict__ xinit,
                                            float* __restrict__ out) {
    int b = blockIdx.x, tid = threadIdx.x;
    int warp = tid >> 5, lane = tid & 31;
    __shared__ float sx[128], su[64], sxn[128];
    if (tid < 128) sx[tid] = xinit[b * 128 + tid];
    __syncthreads();

    for (int t = 0; t < 128; t++) {
        size_t bt = (size_t)b * T_ + t;
        const float* Kb = g_K + ((size_t)t * B_ + b) * (M_ * N_);
        const float* kb = g_k + ((size_t)t * B_ + b) * M_;
        for (int r = warp; r < 64; r += 8) {
            const float* kr = Kb + r * 128;
            float s = kr[lane] * sx[lane] + kr[32 + lane] * sx[32 + lane]
                    + kr[64 + lane] * sx[64 + lane] + kr[96 + lane] * sx[96 + lane];
#pragma unroll
            for (int o = 16; o; o >>= 1) s += __shfl_down_sync(0xffffffffu, s, o);
            if (lane == 0) su[r] = s + kb[r];
        }
        if (tid < 128) out[bt * NT_ + tid] = sx[tid];
        __syncthreads();
        if (tid < 64) out[bt * NT_ + 128 + tid] = su[tid];

        const float* Ab = A + bt * (size_t)(N_ * N_);
        const float* Bb = Bm + bt * (size_t)(N_ * M_);
        for (int r = warp; r < 128; r += 8) {
            const float* ar = Ab + r * 128;
            const float* br = Bb + r * 64;
            float s = ar[lane] * sx[lane] + ar[32 + lane] * sx[32 + lane]
                    + ar[64 + lane] * sx[64 + lane] + ar[96 + lane] * sx[96 + lane]
                    + br[lane] * su[lane] + br[32 + lane] * su[32 + lane];
#pragma unroll
            for (int o = 16; o; o >>= 1) s += __shfl_down_sync(0xffffffffu, s, o);
            if (lane == 0) sxn[r] = s + c1[bt * 128 + r];
        }
        __syncthreads();
        if (tid < 128) sx[tid] = sxn[tid];
        __syncthreads();
    }
}

// ---------------- launch ----------------
extern "C" void kernel_launch(void* const* d_in, const int* in_sizes, int n_in,
                              void* d_out, int out_size) {
    const float *A = 0, *Bm = 0, *c1 = 0, *Q = 0, *p = 0, *xinit = 0;
    for (int i = 0; i < n_in; i++) {
        switch (in_sizes[i]) {
            case 67108864:  A = (const float*)d_in[i]; break;      // 32*128*128*128
            case 33554432:  Bm = (const float*)d_in[i]; break;     // 32*128*128*64
            case 524288:    c1 = (const float*)d_in[i]; break;     // 32*128*128
            case 150994944: Q = (const float*)d_in[i]; break;      // 32*128*192*192
            case 786432:    p = (const float*)d_in[i]; break;      // 32*128*192
            case 4096:      xinit = (const float*)d_in[i]; break;  // 32*128
        }
    }
    float* out = (float*)d_out;

    kzero<<<(B_ * N_ * N_ + 255) / 256, 256>>>();
    for (int t = T_ - 1; t >= 0; t--) {
        k1_VF<<<dim3(7, B_), 256>>>(A, Bm, c1, t);
        k2_Qhat<<<dim3(8, B_), 256>>>(A, Bm, Q, p, t);
        k3a_chol<<<B_, 256>>>();
        k3b_solve<<<dim3(4, B_), 256>>>(t);
    }
    kfwd<<<B_, 256>>>(A, Bm, c1, xinit, out);
}

// round 11
// speedup vs baseline: 1.3197x; 1.1052x over previous
#include <cuda_runtime.h>

#define B_ 32
#define T_ 128
#define N_ 128
#define M_ 64
#define NT_ 192

// ---------------- device scratch (no allocations allowed) ----------------
__device__ float g_V[B_ * N_ * N_];
__device__ float g_v[B_ * N_];
__device__ float g_w[B_ * N_];
__device__ float g_VF[B_ * N_ * NT_];
__device__ float g_Qxx[B_ * N_ * N_];
__device__ float g_Qu[B_ * M_ * NT_];   // rows 0..63: cols 0..127 = Qux, 128..191 = Quu
__device__ float g_qhat[B_ * NT_];
__device__ float g_K[(size_t)T_ * B_ * M_ * N_];
__device__ float g_k[T_ * B_ * M_];

#define FMA16(a, bq)                                                                   \
    acc[0][0] += a.x * bq.x; acc[0][1] += a.x * bq.y; acc[0][2] += a.x * bq.z; acc[0][3] += a.x * bq.w; \
    acc[1][0] += a.y * bq.x; acc[1][1] += a.y * bq.y; acc[1][2] += a.y * bq.z; acc[1][3] += a.y * bq.w; \
    acc[2][0] += a.z * bq.x; acc[2][1] += a.z * bq.y; acc[2][2] += a.z * bq.z; acc[2][3] += a.z * bq.w; \
    acc[3][0] += a.w * bq.x; acc[3][1] += a.w * bq.y; acc[3][2] += a.w * bq.z; acc[3][3] += a.w * bq.w;

// ---------------- init ----------------
__global__ void kzero() {
    int idx = blockIdx.x * 256 + threadIdx.x;
    if (idx < B_ * N_ * N_) g_V[idx] = 0.0f;
    if (idx < B_ * N_) g_v[idx] = 0.0f;
}

// ---------------- k1: VF = V @ [A|B]  (uses V symmetry), w = V c + v ----------------
__global__ __launch_bounds__(256) void k1_VF(const float* __restrict__ A,
                                             const float* __restrict__ Bm,
                                             const float* __restrict__ c1, int t) {
    int b = blockIdx.y;
    int bx = blockIdx.x;
    int tid = threadIdx.x;
    const float* Vb = g_V + b * N_ * N_;
    size_t bt = (size_t)b * T_ + t;

    if (bx == 6) {  // w = V c + v  (V symmetric -> coalesced column read)
        __shared__ float cs[128];
        if (tid < 128) cs[tid] = c1[bt * 128 + tid];
        __syncthreads();
        if (tid < 128) {
            float acc = g_v[b * 128 + tid];
#pragma unroll 8
            for (int m = 0; m < 128; m++) acc += Vb[m * 128 + tid] * cs[m];
            g_w[b * 128 + tid] = acc;
        }
        return;
    }

    int tr = bx / 3, tc = bx % 3;
    int rb = tr * 64, cb = tc * 64;
    const float* Fsrc; int ldF, coff;
    if (cb < 128) { Fsrc = A + bt * (size_t)(N_ * N_); ldF = 128; coff = cb; }
    else          { Fsrc = Bm + bt * (size_t)(N_ * M_); ldF = 64;  coff = 0;  }

    __shared__ float As[16][64];
    __shared__ float Bs[16][64];
    int tx = tid & 15, ty = tid >> 4;
    float acc[4][4] = {};

    for (int kb = 0; kb < 8; kb++) {
        int k = kb * 16 + ty;
        // V symmetric: V[row][k] == V[k][row]
        *(float4*)&As[ty][tx * 4] = *(const float4*)(Vb + k * 128 + rb + tx * 4);
        *(float4*)&Bs[ty][tx * 4] = *(const float4*)(Fsrc + (size_t)k * ldF + coff + tx * 4);
        __syncthreads();
#pragma unroll
        for (int kk = 0; kk < 16; kk++) {
            float4 a = *(float4*)&As[kk][ty * 4];
            float4 bq = *(float4*)&Bs[kk][tx * 4];
            FMA16(a, bq)
        }
        __syncthreads();
    }
    float* outp = g_VF + b * N_ * NT_;
#pragma unroll
    for (int i = 0; i < 4; i++) {
        *(float4*)(outp + (rb + ty * 4 + i) * NT_ + cb + tx * 4) =
            make_float4(acc[i][0], acc[i][1], acc[i][2], acc[i][3]);
    }
}

// ---------------- k2: Qxx (3 tiles + mirror) ; [Qux|Quu] = Q_u + B^T VF ; qhat ----------------
// bx: 0=(0,0)  1=(1,0)+mirror->(0,1)  2=(1,1)  3,4,5=Qu jb=0,64,128  6=qhat
__global__ __launch_bounds__(256) void k2_Qhat(const float* __restrict__ A,
                                               const float* __restrict__ Bm,
                                               const float* __restrict__ Q,
                                               const float* __restrict__ p, int t) {
    int b = blockIdx.y, bx = blockIdx.x, tid = threadIdx.x;
    size_t bt = (size_t)b * T_ + t;

    if (bx == 6) {  // qhat = p + F^T w
        __shared__ float ws[128];
        if (tid < 128) ws[tid] = g_w[b * 128 + tid];
        __syncthreads();
        if (tid < 192) {
            float acc = p[bt * NT_ + tid];
            if (tid < 128) {
                const float* Ab = A + bt * (size_t)(N_ * N_);
#pragma unroll 4
                for (int n = 0; n < 128; n++) acc += Ab[n * 128 + tid] * ws[n];
            } else {
                const float* Bb = Bm + bt * (size_t)(N_ * M_);
                int j = tid - 128;
#pragma unroll 4
                for (int n = 0; n < 128; n++) acc += Bb[n * 64 + j] * ws[n];
            }
            g_qhat[b * NT_ + tid] = acc;
        }
        return;
    }

    bool isQxx = bx < 3;
    int ib, jb; const float* Asrc; int lda, aoff;
    if (isQxx) {
        ib = (bx == 0) ? 0 : 64;
        jb = (bx == 2) ? 64 : 0;
        Asrc = A + bt * (size_t)(N_ * N_); lda = 128; aoff = ib;
    } else {
        ib = 0; jb = (bx - 3) * 64; Asrc = Bm + bt * (size_t)(N_ * M_); lda = 64; aoff = 0;
    }

    __shared__ float As[16][64];
    __shared__ float Bs[16][64];
    __shared__ float outS[64 * 65];
    int tx = tid & 15, ty = tid >> 4;
    const float* VFb = g_VF + b * N_ * NT_;
    float acc[4][4] = {};

    for (int kb = 0; kb < 8; kb++) {
        int k = kb * 16 + ty;
        *(float4*)&As[ty][tx * 4] = *(const float4*)(Asrc + (size_t)k * lda + aoff + tx * 4);
        *(float4*)&Bs[ty][tx * 4] = *(const float4*)(VFb + k * NT_ + jb + tx * 4);
        __syncthreads();
#pragma unroll
        for (int kk = 0; kk < 16; kk++) {
            float4 a = *(float4*)&As[kk][ty * 4];
            float4 bq = *(float4*)&Bs[kk][tx * 4];
            FMA16(a, bq)
        }
        __syncthreads();
    }

    const float* Qb = Q + bt * (size_t)(NT_ * NT_);
    if (isQxx) {
        float* outp = g_Qxx + b * N_ * N_;
#pragma unroll
        for (int i = 0; i < 4; i++) {
            int r = ib + ty * 4 + i, cc = jb + tx * 4;
            float4 q4 = *(const float4*)(Qb + (size_t)r * NT_ + cc);
            float4 o = make_float4(acc[i][0] + q4.x, acc[i][1] + q4.y,
                                   acc[i][2] + q4.z, acc[i][3] + q4.w);
            *(float4*)(outp + r * N_ + cc) = o;
            if (bx == 1) {  // buffer for mirror (scalar stores: pad-65 rows)
                int rl = ty * 4 + i, cl = tx * 4;
                outS[rl * 65 + cl]     = o.x;
                outS[rl * 65 + cl + 1] = o.y;
                outS[rl * 65 + cl + 2] = o.z;
                outS[rl * 65 + cl + 3] = o.w;
            }
        }
        if (bx == 1) {  // mirror: Qxx[cl][64+rl] = tile[rl][cl]
            __syncthreads();
            for (int idx = tid; idx < 64 * 64; idx += 256) {
                int cl = idx >> 6, rl = idx & 63;
                outp[cl * N_ + 64 + rl] = outS[rl * 65 + cl];
            }
        }
    } else {
        float* outp = g_Qu + b * M_ * NT_;
#pragma unroll
        for (int i = 0; i < 4; i++) {
            int r = ty * 4 + i, cc = jb + tx * 4;
            float4 q4 = *(const float4*)(Qb + (size_t)(128 + r) * NT_ + cc);
            *(float4*)(outp + r * NT_ + cc) =
                make_float4(acc[i][0] + q4.x, acc[i][1] + q4.y, acc[i][2] + q4.z, acc[i][3] + q4.w);
        }
    }
}

// ---------------- k3: (redundant) blocked Cholesky + column-group solve + K/k + Vn + vn ----------------
// grid (4, B_), 512 threads. CTA cg handles Qux columns [cg*32, cg*32+32); cg==0 also qu.
__global__ __launch_bounds__(512) void k3_solve(int t) {
    __shared__ __align__(16) float sL[64 * 68];
    __shared__ __align__(16) float sPT[16 * 68];
    __shared__ __align__(16) float sRb[64 * 36];
    __shared__ float sInvD[64];
    __shared__ float sk[64];
    int b = blockIdx.y, cg = blockIdx.x, tid = threadIdx.x;
    int col0 = cg * 32;
    int ncols = (cg == 0) ? 33 : 32;   // local col 32 = qu (cg 0 only)
    const float* Qub = g_Qu + b * M_ * NT_;

    // stage Quu into sL and the RHS slice into sRb (float4, coalesced)
    for (int idx = tid; idx < 64 * 16; idx += 512) {
        int i = idx >> 4, j4 = idx & 15;
        *(float4*)&sL[i * 68 + j4 * 4] = *(const float4*)(Qub + i * NT_ + 128 + j4 * 4);
    }
    for (int idx = tid; idx < 64 * 8; idx += 512) {
        int i = idx >> 3, c4 = idx & 7;
        *(float4*)&sRb[i * 36 + c4 * 4] = *(const float4*)(Qub + i * NT_ + col0 + c4 * 4);
    }
    if (cg == 0 && tid < 64) sRb[tid * 36 + 32] = g_qhat[b * NT_ + 128 + tid];
    __syncthreads();

    // ---- blocked lower Cholesky, 16-wide panels (redundant per CTA) ----
    for (int kb = 0; kb < 64; kb += 16) {
        // 1) factor 16x16 diagonal block in registers via shfl (warp 0)
        if (tid < 32) {
            int l = tid & 15;
            int row = kb + l;
            float a[16];
#pragma unroll
            for (int i = 0; i < 16; i++) a[i] = sL[row * 68 + kb + i];
#pragma unroll
            for (int i = 0; i < 16; i++) {
                float aii = __shfl_sync(0xffffffffu, a[i], i);
                float dinv = rsqrtf(aii);
                a[i] *= dinv;
                if (tid == i) sInvD[kb + i] = dinv;
#pragma unroll
                for (int c = i + 1; c < 16; c++) {
                    float lci = __shfl_sync(0xffffffffu, a[i], c);
                    a[c] -= a[i] * lci;
                }
            }
            if (tid < 16) {
#pragma unroll
                for (int i = 0; i < 16; i++)
                    if (i <= l) sL[row * 68 + kb + i] = a[i];
            }
        }
        __syncthreads();

        int rem = 48 - kb;
        if (rem > 0) {
            // 2) panel solve: one thread per row r = kb+16..63
            if (tid < rem) {
                int r = kb + 16 + tid;
                float a[16];
#pragma unroll
                for (int i = 0; i < 16; i++) a[i] = sL[r * 68 + kb + i];
#pragma unroll
                for (int i = 0; i < 16; i++) {
                    float s = a[i];
#pragma unroll
                    for (int m = 0; m < i; m++) s -= a[m] * sL[(kb + i) * 68 + kb + m];
                    a[i] = s * sInvD[kb + i];
                }
#pragma unroll
                for (int i = 0; i < 16; i++) {
                    sL[r * 68 + kb + i] = a[i];
                    sPT[i * 68 + r] = a[i];
                }
            }
            __syncthreads();

            // 3) trailing rank-16 update, register-tiled float4 strips
            //    rows jr = kb+16..63; strips of 4 cols; junk above diag is harmless
            int nstrip = rem * 16;
            for (int idx = tid; idx < nstrip; idx += 512) {
                int jr = kb + 16 + (idx >> 4);
                int c4 = (idx & 15) * 4;
                if (c4 >= kb + 16 && c4 <= jr) {
                    float4 s = *(float4*)&sL[jr * 68 + c4];
#pragma unroll
                    for (int m = 0; m < 16; m++) {
                        float pj = sPT[m * 68 + jr];
                        float4 pc = *(const float4*)&sPT[m * 68 + c4];
                        s.x -= pj * pc.x; s.y -= pj * pc.y;
                        s.z -= pj * pc.z; s.w -= pj * pc.w;
                    }
                    *(float4*)&sL[jr * 68 + c4] = s;
                }
            }
            __syncthreads();
        }
    }

    // ---- forward substitution: L y = rhs (in place in sRb) ----
    for (int jb = 0; jb < 4; jb++) {
        int base = jb * 16;
        if (tid < ncols) {
            int c = tid;
            float yl[16];
#pragma unroll
            for (int r = 0; r < 16; r++) yl[r] = sRb[(base + r) * 36 + c];
#pragma unroll
            for (int r = 0; r < 16; r++) {
                float s = yl[r];
#pragma unroll
                for (int m = 0; m < r; m++) s -= sL[(base + r) * 68 + base + m] * yl[m];
                yl[r] = s * sInvD[base + r];
                sRb[(base + r) * 36 + c] = yl[r];
            }
        }
        __syncthreads();
        int ng = 3 - jb;
        if (ng > 0 && tid < ncols * ng) {
            int c = tid % ncols;
            int g = tid / ncols;
            int r0 = base + 16 + g * 16;
            float yv[16];
#pragma unroll
            for (int m = 0; m < 16; m++) yv[m] = sRb[(base + m) * 36 + c];
#pragma unroll
            for (int r = 0; r < 16; r++) {
                float s = sRb[(r0 + r) * 36 + c];
#pragma unroll
                for (int m = 0; m < 16; m++)
                    s -= sL[(r0 + r) * 68 + base + m] * yv[m];
                sRb[(r0 + r) * 36 + c] = s;
            }
        }
        __syncthreads();
    }

    // ---- backward substitution: L^T x = y (L read transposed, broadcast) ----
    for (int jb = 3; jb >= 0; jb--) {
        int base = jb * 16;
        if (tid < ncols) {
            int c = tid;
            float yl[16];
#pragma unroll
            for (int r = 0; r < 16; r++) yl[r] = sRb[(base + r) * 36 + c];
#pragma unroll
            for (int r = 15; r >= 0; r--) {
                float s = yl[r];
#pragma unroll
                for (int m = r + 1; m < 16; m++) s -= sL[(base + m) * 68 + base + r] * yl[m];
                yl[r] = s * sInvD[base + r];
                sRb[(base + r) * 36 + c] = yl[r];
            }
        }
        __syncthreads();
        if (jb > 0 && tid < ncols * jb) {
            int c = tid % ncols;
            int g = tid / ncols;
            int r0 = g * 16;
            float yv[16];
#pragma unroll
            for (int m = 0; m < 16; m++) yv[m] = sRb[(base + m) * 36 + c];
#pragma unroll
            for (int r = 0; r < 16; r++) {
                float s = sRb[(r0 + r) * 36 + c];
#pragma unroll
                for (int m = 0; m < 16; m++)
                    s -= sL[(base + m) * 68 + (r0 + r)] * yv[m];
                sRb[(r0 + r) * 36 + c] = s;
            }
        }
        __syncthreads();
    }

    // ---- store K slice; cg 0 stores k ----
    {
        float* Kb = g_K + ((size_t)t * B_ + b) * (M_ * N_);
        for (int idx = tid; idx < 64 * 32; idx += 512) {
            int j = idx >> 5, cc = idx & 31;
            Kb[j * 128 + col0 + cc] = -sRb[j * 36 + cc];
        }
        if (cg == 0 && tid < 64) {
            float kv = -sRb[tid * 36 + 32];
            g_k[((size_t)t * B_ + b) * M_ + tid] = kv;
            sk[tid] = kv;
        }
    }
    __syncthreads();

    // ---- vn = qx + Qux^T k (cg 0 only) ----
    if (cg == 0 && tid < 128) {
        float acc = g_qhat[b * NT_ + tid];
#pragma unroll 8
        for (int m = 0; m < 64; m++) acc += Qub[m * NT_ + tid] * sk[m];
        g_v[b * 128 + tid] = acc;
    }

    // ---- Vn slice: Vn[:, col0..col0+31] = Qxx[:, cols] - Qux^T @ y(slice) ----
    {
        int tx = tid & 7;         // col strip: cols col0 + tx*4 .. +3
        int ty = tid >> 3;        // 0..63 -> rows ty*2, ty*2+1
        float acc2[2][4] = {};
#pragma unroll 4
        for (int m = 0; m < 64; m++) {
            float4 yv = *(const float4*)&sRb[m * 36 + tx * 4];
            const float* qrow = Qub + m * NT_ + ty * 2;
            float q0 = qrow[0], q1 = qrow[1];
            acc2[0][0] += q0 * yv.x; acc2[0][1] += q0 * yv.y;
            acc2[0][2] += q0 * yv.z; acc2[0][3] += q0 * yv.w;
            acc2[1][0] += q1 * yv.x; acc2[1][1] += q1 * yv.y;
            acc2[1][2] += q1 * yv.z; acc2[1][3] += q1 * yv.w;
        }
        const float* Qxxb = g_Qxx + b * N_ * N_;
        float* Vb = g_V + b * N_ * N_;
#pragma unroll
        for (int rr = 0; rr < 2; rr++) {
            int i = ty * 2 + rr;
            float4 q4 = *(const float4*)(Qxxb + i * N_ + col0 + tx * 4);
            *(float4*)(Vb + i * N_ + col0 + tx * 4) =
                make_float4(q4.x - acc2[rr][0], q4.y - acc2[rr][1],
                            q4.z - acc2[rr][2], q4.w - acc2[rr][3]);
        }
    }
}

// ---------------- forward rollout ----------------
__global__ __launch_bounds__(256) void kfwd(const float* __restrict__ A,
                                            const float* __restrict__ Bm,
                                            const float* __restrict__ c1,
                                            const float* __restrict__ xinit,
                                            float* __restrict__ out) {
    int b = blockIdx.x, tid = threadIdx.x;
    int warp = tid >> 5, lane = tid & 31;
    __shared__ float sx[128], su[64], sxn[128];
    if (tid < 128) sx[tid] = xinit[b * 128 + tid];
    __syncthreads();

    for (int t = 0; t < 128; t++) {
        size_t bt = (size_t)b * T_ + t;
        const float* Kb = g_K + ((size_t)t * B_ + b) * (M_ * N_);
        const float* kb = g_k + ((size_t)t * B_ + b) * M_;
        for (int r = warp; r < 64; r += 8) {
            const float* kr = Kb + r * 128;
            float s = kr[lane] * sx[lane] + kr[32 + lane] * sx[32 + lane]
                    + kr[64 + lane] * sx[64 + lane] + kr[96 + lane] * sx[96 + lane];
#pragma unroll
            for (int o = 16; o; o >>= 1) s += __shfl_down_sync(0xffffffffu, s, o);
            if (lane == 0) su[r] = s + kb[r];
        }
        if (tid < 128) out[bt * NT_ + tid] = sx[tid];
        __syncthreads();
        if (tid < 64) out[bt * NT_ + 128 + tid] = su[tid];

        const float* Ab = A + bt * (size_t)(N_ * N_);
        const float* Bb = Bm + bt * (size_t)(N_ * M_);
        for (int r = warp; r < 128; r += 8) {
            const float* ar = Ab + r * 128;
            const float* br = Bb + r * 64;
            float s = ar[lane] * sx[lane] + ar[32 + lane] * sx[32 + lane]
                    + ar[64 + lane] * sx[64 + lane] + ar[96 + lane] * sx[96 + lane]
                    + br[lane] * su[lane] + br[32 + lane] * su[32 + lane];
#pragma unroll
            for (int o = 16; o; o >>= 1) s += __shfl_down_sync(0xffffffffu, s, o);
            if (lane == 0) sxn[r] = s + c1[bt * 128 + r];
        }
        __syncthreads();
        if (tid < 128) sx[tid] = sxn[tid];
        __syncthreads();
    }
}

// ---------------- launch ----------------
extern "C" void kernel_launch(void* const* d_in, const int* in_sizes, int n_in,
                              void* d_out, int out_size) {
    const float *A = 0, *Bm = 0, *c1 = 0, *Q = 0, *p = 0, *xinit = 0;
    for (int i = 0; i < n_in; i++) {
        switch (in_sizes[i]) {
            case 67108864:  A = (const float*)d_in[i]; break;      // 32*128*128*128
            case 33554432:  Bm = (const float*)d_in[i]; break;     // 32*128*128*64
            case 524288:    c1 = (const float*)d_in[i]; break;     // 32*128*128
            case 150994944: Q = (const float*)d_in[i]; break;      // 32*128*192*192
            case 786432:    p = (const float*)d_in[i]; break;      // 32*128*192
            case 4096:      xinit = (const float*)d_in[i]; break;  // 32*128
        }
    }
    float* out = (float*)d_out;

    kzero<<<(B_ * N_ * N_ + 255) / 256, 256>>>();
    for (int t = T_ - 1; t >= 0; t--) {
        k1_VF<<<dim3(7, B_), 256>>>(A, Bm, c1, t);
        k2_Qhat<<<dim3(7, B_), 256>>>(A, Bm, Q, p, t);
        k3_solve<<<dim3(4, B_), 512>>>(t);
    }
    kfwd<<<B_, 256>>>(A, Bm, c1, xinit, out);
}

// round 12
// speedup vs baseline: 1.3570x; 1.0282x over previous
#include <cuda_runtime.h>

#define B_ 32
#define T_ 128
#define N_ 128
#define M_ 64
#define NT_ 192

// ---------------- device scratch (no allocations allowed) ----------------
__device__ float g_V[B_ * N_ * N_];
__device__ float g_v[B_ * N_];
__device__ float g_w[B_ * N_];
__device__ float g_VF[B_ * N_ * NT_];
__device__ float g_Qxx[B_ * N_ * N_];
__device__ float g_Qu[B_ * M_ * NT_];   // rows 0..63: cols 0..127 = Qux, 128..191 = Quu
__device__ float g_qhat[B_ * NT_];
__device__ float g_K[(size_t)T_ * B_ * M_ * N_];
__device__ float g_k[T_ * B_ * M_];

#define FMA16(a, bq)                                                                   \
    acc[0][0] += a.x * bq.x; acc[0][1] += a.x * bq.y; acc[0][2] += a.x * bq.z; acc[0][3] += a.x * bq.w; \
    acc[1][0] += a.y * bq.x; acc[1][1] += a.y * bq.y; acc[1][2] += a.y * bq.z; acc[1][3] += a.y * bq.w; \
    acc[2][0] += a.z * bq.x; acc[2][1] += a.z * bq.y; acc[2][2] += a.z * bq.z; acc[2][3] += a.z * bq.w; \
    acc[3][0] += a.w * bq.x; acc[3][1] += a.w * bq.y; acc[3][2] += a.w * bq.z; acc[3][3] += a.w * bq.w;

// ---------------- init ----------------
__global__ void kzero() {
    int idx = blockIdx.x * 256 + threadIdx.x;
    if (idx < B_ * N_ * N_) g_V[idx] = 0.0f;
    if (idx < B_ * N_) g_v[idx] = 0.0f;
}

// ---------------- k1: VF = V @ [A|B]  (uses V symmetry), w = V c + v ----------------
__global__ __launch_bounds__(256) void k1_VF(const float* __restrict__ A,
                                             const float* __restrict__ Bm,
                                             const float* __restrict__ c1, int t) {
    int b = blockIdx.y;
    int bx = blockIdx.x;
    int tid = threadIdx.x;
    const float* Vb = g_V + b * N_ * N_;
    size_t bt = (size_t)b * T_ + t;

    if (bx == 6) {  // w = V c + v  (V symmetric -> coalesced column read)
        __shared__ float cs[128];
        if (tid < 128) cs[tid] = c1[bt * 128 + tid];
        __syncthreads();
        if (tid < 128) {
            float acc = g_v[b * 128 + tid];
#pragma unroll 8
            for (int m = 0; m < 128; m++) acc += Vb[m * 128 + tid] * cs[m];
            g_w[b * 128 + tid] = acc;
        }
        return;
    }

    int tr = bx / 3, tc = bx % 3;
    int rb = tr * 64, cb = tc * 64;
    const float* Fsrc; int ldF, coff;
    if (cb < 128) { Fsrc = A + bt * (size_t)(N_ * N_); ldF = 128; coff = cb; }
    else          { Fsrc = Bm + bt * (size_t)(N_ * M_); ldF = 64;  coff = 0;  }

    __shared__ float As[16][64];
    __shared__ float Bs[16][64];
    int tx = tid & 15, ty = tid >> 4;
    float acc[4][4] = {};

    for (int kb = 0; kb < 8; kb++) {
        int k = kb * 16 + ty;
        // V symmetric: V[row][k] == V[k][row]
        *(float4*)&As[ty][tx * 4] = *(const float4*)(Vb + k * 128 + rb + tx * 4);
        *(float4*)&Bs[ty][tx * 4] = *(const float4*)(Fsrc + (size_t)k * ldF + coff + tx * 4);
        __syncthreads();
#pragma unroll
        for (int kk = 0; kk < 16; kk++) {
            float4 a = *(float4*)&As[kk][ty * 4];
            float4 bq = *(float4*)&Bs[kk][tx * 4];
            FMA16(a, bq)
        }
        __syncthreads();
    }
    float* outp = g_VF + b * N_ * NT_;
#pragma unroll
    for (int i = 0; i < 4; i++) {
        *(float4*)(outp + (rb + ty * 4 + i) * NT_ + cb + tx * 4) =
            make_float4(acc[i][0], acc[i][1], acc[i][2], acc[i][3]);
    }
}

// ---------------- k2: Qxx (3 tiles + mirror) ; [Qux|Quu] = Q_u + B^T VF ; qhat ----------------
// bx: 0=(0,0)  1=(1,0)+mirror->(0,1)  2=(1,1)  3,4,5=Qu jb=0,64,128  6=qhat
__global__ __launch_bounds__(256) void k2_Qhat(const float* __restrict__ A,
                                               const float* __restrict__ Bm,
                                               const float* __restrict__ Q,
                                               const float* __restrict__ p, int t) {
    int b = blockIdx.y, bx = blockIdx.x, tid = threadIdx.x;
    size_t bt = (size_t)b * T_ + t;

    if (bx == 6) {  // qhat = p + F^T w
        __shared__ float ws[128];
        if (tid < 128) ws[tid] = g_w[b * 128 + tid];
        __syncthreads();
        if (tid < 192) {
            float acc = p[bt * NT_ + tid];
            if (tid < 128) {
                const float* Ab = A + bt * (size_t)(N_ * N_);
#pragma unroll 4
                for (int n = 0; n < 128; n++) acc += Ab[n * 128 + tid] * ws[n];
            } else {
                const float* Bb = Bm + bt * (size_t)(N_ * M_);
                int j = tid - 128;
#pragma unroll 4
                for (int n = 0; n < 128; n++) acc += Bb[n * 64 + j] * ws[n];
            }
            g_qhat[b * NT_ + tid] = acc;
        }
        return;
    }

    bool isQxx = bx < 3;
    int ib, jb; const float* Asrc; int lda, aoff;
    if (isQxx) {
        ib = (bx == 0) ? 0 : 64;
        jb = (bx == 2) ? 64 : 0;
        Asrc = A + bt * (size_t)(N_ * N_); lda = 128; aoff = ib;
    } else {
        ib = 0; jb = (bx - 3) * 64; Asrc = Bm + bt * (size_t)(N_ * M_); lda = 64; aoff = 0;
    }

    __shared__ float As[16][64];
    __shared__ float Bs[16][64];
    __shared__ float outS[64 * 65];
    int tx = tid & 15, ty = tid >> 4;
    const float* VFb = g_VF + b * N_ * NT_;
    float acc[4][4] = {};

    for (int kb = 0; kb < 8; kb++) {
        int k = kb * 16 + ty;
        *(float4*)&As[ty][tx * 4] = *(const float4*)(Asrc + (size_t)k * lda + aoff + tx * 4);
        *(float4*)&Bs[ty][tx * 4] = *(const float4*)(VFb + k * NT_ + jb + tx * 4);
        __syncthreads();
#pragma unroll
        for (int kk = 0; kk < 16; kk++) {
            float4 a = *(float4*)&As[kk][ty * 4];
            float4 bq = *(float4*)&Bs[kk][tx * 4];
            FMA16(a, bq)
        }
        __syncthreads();
    }

    const float* Qb = Q + bt * (size_t)(NT_ * NT_);
    if (isQxx) {
        float* outp = g_Qxx + b * N_ * N_;
#pragma unroll
        for (int i = 0; i < 4; i++) {
            int r = ib + ty * 4 + i, cc = jb + tx * 4;
            float4 q4 = *(const float4*)(Qb + (size_t)r * NT_ + cc);
            float4 o = make_float4(acc[i][0] + q4.x, acc[i][1] + q4.y,
                                   acc[i][2] + q4.z, acc[i][3] + q4.w);
            *(float4*)(outp + r * N_ + cc) = o;
            if (bx == 1) {  // buffer for mirror (scalar stores: pad-65 rows)
                int rl = ty * 4 + i, cl = tx * 4;
                outS[rl * 65 + cl]     = o.x;
                outS[rl * 65 + cl + 1] = o.y;
                outS[rl * 65 + cl + 2] = o.z;
                outS[rl * 65 + cl + 3] = o.w;
            }
        }
        if (bx == 1) {  // mirror: Qxx[cl][64+rl] = tile[rl][cl]
            __syncthreads();
            for (int idx = tid; idx < 64 * 64; idx += 256) {
                int cl = idx >> 6, rl = idx & 63;
                outp[cl * N_ + 64 + rl] = outS[rl * 65 + cl];
            }
        }
    } else {
        float* outp = g_Qu + b * M_ * NT_;
#pragma unroll
        for (int i = 0; i < 4; i++) {
            int r = ty * 4 + i, cc = jb + tx * 4;
            float4 q4 = *(const float4*)(Qb + (size_t)(128 + r) * NT_ + cc);
            *(float4*)(outp + r * NT_ + cc) =
                make_float4(acc[i][0] + q4.x, acc[i][1] + q4.y, acc[i][2] + q4.z, acc[i][3] + q4.w);
        }
    }
}

// ---------------- k3: Cholesky with FUSED forward substitution + backward + K/k + Vn + vn ----------------
// grid (4, B_), 512 threads. CTA cg handles Qux columns [cg*32, cg*32+32); cg==0 also qu.
__global__ __launch_bounds__(512) void k3_solve(int t) {
    __shared__ __align__(16) float sL[64 * 68];
    __shared__ __align__(16) float sPT[16 * 68];
    __shared__ __align__(16) float sRb[64 * 36];
    __shared__ float sInvD[64];
    __shared__ float sk[64];
    int b = blockIdx.y, cg = blockIdx.x, tid = threadIdx.x;
    int col0 = cg * 32;
    int ncols = (cg == 0) ? 33 : 32;   // local col 32 = qu (cg 0 only)
    const float* Qub = g_Qu + b * M_ * NT_;

    // stage Quu into sL and the RHS slice into sRb (float4, coalesced)
    for (int idx = tid; idx < 64 * 16; idx += 512) {
        int i = idx >> 4, j4 = idx & 15;
        *(float4*)&sL[i * 68 + j4 * 4] = *(const float4*)(Qub + i * NT_ + 128 + j4 * 4);
    }
    for (int idx = tid; idx < 64 * 8; idx += 512) {
        int i = idx >> 3, c4 = idx & 7;
        *(float4*)&sRb[i * 36 + c4 * 4] = *(const float4*)(Qub + i * NT_ + col0 + c4 * 4);
    }
    if (cg == 0 && tid < 64) sRb[tid * 36 + 32] = g_qhat[b * NT_ + 128 + tid];
    __syncthreads();

    // ---- blocked lower Cholesky with fused forward substitution ----
    for (int kb = 0; kb < 64; kb += 16) {
        // W1: factor 16x16 diagonal block in registers via shfl (warp 0)
        if (tid < 32) {
            int l = tid & 15;
            int row = kb + l;
            float a[16];
#pragma unroll
            for (int i = 0; i < 16; i++) a[i] = sL[row * 68 + kb + i];
#pragma unroll
            for (int i = 0; i < 16; i++) {
                float aii = __shfl_sync(0xffffffffu, a[i], i);
                float dinv = rsqrtf(aii);
                a[i] *= dinv;
                if (tid == i) sInvD[kb + i] = dinv;
#pragma unroll
                for (int c = i + 1; c < 16; c++) {
                    float lci = __shfl_sync(0xffffffffu, a[i], c);
                    a[c] -= a[i] * lci;
                }
            }
            if (tid < 16) {
#pragma unroll
                for (int i = 0; i < 16; i++)
                    if (i <= l) sL[row * 68 + kb + i] = a[i];
            }
        }
        __syncthreads();

        int rem = 48 - kb;
        // W2: chol panel solve (tid < rem)  ||  RHS diag-solve (tid in [64, 64+ncols))
        if (tid < rem) {
            int r = kb + 16 + tid;
            float a[16];
#pragma unroll
            for (int i = 0; i < 16; i++) a[i] = sL[r * 68 + kb + i];
#pragma unroll
            for (int i = 0; i < 16; i++) {
                float s0 = 0.f, s1 = 0.f;
                int m = 0;
#pragma unroll
                for (; m + 1 < i; m += 2) {
                    s0 += a[m] * sL[(kb + i) * 68 + kb + m];
                    s1 += a[m + 1] * sL[(kb + i) * 68 + kb + m + 1];
                }
                if (m < i) s0 += a[m] * sL[(kb + i) * 68 + kb + m];
                a[i] = (a[i] - s0 - s1) * sInvD[kb + i];
            }
#pragma unroll
            for (int i = 0; i < 16; i++) {
                sL[r * 68 + kb + i] = a[i];
                sPT[i * 68 + r] = a[i];
            }
        } else if (tid >= 64 && tid < 64 + ncols) {
            int c = tid - 64;
            float yl[16];
#pragma unroll
            for (int r = 0; r < 16; r++) yl[r] = sRb[(kb + r) * 36 + c];
#pragma unroll
            for (int r = 0; r < 16; r++) {
                float s0 = 0.f, s1 = 0.f;
                int m = 0;
#pragma unroll
                for (; m + 1 < r; m += 2) {
                    s0 += sL[(kb + r) * 68 + kb + m] * yl[m];
                    s1 += sL[(kb + r) * 68 + kb + m + 1] * yl[m + 1];
                }
                if (m < r) s0 += sL[(kb + r) * 68 + kb + m] * yl[m];
                yl[r] = (yl[r] - s0 - s1) * sInvD[kb + r];
                sRb[(kb + r) * 36 + c] = yl[r];
            }
        }
        __syncthreads();

        // W3: chol trailing strips (tid < 384) || RHS bulk elimination (tid >= 384)
        if (rem > 0) {
            if (tid < 384) {
                int nstrip = rem * 16;
                for (int idx = tid; idx < nstrip; idx += 384) {
                    int jr = kb + 16 + (idx >> 4);
                    int c4 = (idx & 15) * 4;
                    if (c4 >= kb + 16 && c4 <= jr) {
                        float4 s = *(float4*)&sL[jr * 68 + c4];
#pragma unroll
                        for (int m = 0; m < 16; m++) {
                            float pj = sPT[m * 68 + jr];
                            float4 pc = *(const float4*)&sPT[m * 68 + c4];
                            s.x -= pj * pc.x; s.y -= pj * pc.y;
                            s.z -= pj * pc.z; s.w -= pj * pc.w;
                        }
                        *(float4*)&sL[jr * 68 + c4] = s;
                    }
                }
            } else {
                int slot = tid - 384;
                int ng = rem >> 4;   // 3, 2, 1
                if (slot < ncols * ng) {
                    int c = slot % ncols;
                    int g = slot / ncols;
                    int r0 = kb + 16 + g * 16;
                    float yv[16];
#pragma unroll
                    for (int m = 0; m < 16; m++) yv[m] = sRb[(kb + m) * 36 + c];
#pragma unroll
                    for (int r = 0; r < 16; r++) {
                        float s = sRb[(r0 + r) * 36 + c];
#pragma unroll
                        for (int m = 0; m < 16; m++)
                            s -= sL[(r0 + r) * 68 + kb + m] * yv[m];
                        sRb[(r0 + r) * 36 + c] = s;
                    }
                }
            }
            __syncthreads();
        }
    }

    // ---- backward substitution: L^T x = y (L read transposed, broadcast) ----
    for (int jb = 3; jb >= 0; jb--) {
        int base = jb * 16;
        if (tid < ncols) {
            int c = tid;
            float yl[16];
#pragma unroll
            for (int r = 0; r < 16; r++) yl[r] = sRb[(base + r) * 36 + c];
#pragma unroll
            for (int r = 15; r >= 0; r--) {
                float s0 = 0.f, s1 = 0.f;
                int m = r + 1;
#pragma unroll
                for (; m + 1 < 16; m += 2) {
                    s0 += sL[(base + m) * 68 + base + r] * yl[m];
                    s1 += sL[(base + m + 1) * 68 + base + r] * yl[m + 1];
                }
                if (m < 16) s0 += sL[(base + m) * 68 + base + r] * yl[m];
                yl[r] = (yl[r] - s0 - s1) * sInvD[base + r];
                sRb[(base + r) * 36 + c] = yl[r];
            }
        }
        __syncthreads();
        if (jb > 0 && tid < ncols * jb) {
            int c = tid % ncols;
            int g = tid / ncols;
            int r0 = g * 16;
            float yv[16];
#pragma unroll
            for (int m = 0; m < 16; m++) yv[m] = sRb[(base + m) * 36 + c];
#pragma unroll
            for (int r = 0; r < 16; r++) {
                float s = sRb[(r0 + r) * 36 + c];
#pragma unroll
                for (int m = 0; m < 16; m++)
                    s -= sL[(base + m) * 68 + (r0 + r)] * yv[m];
                sRb[(r0 + r) * 36 + c] = s;
            }
        }
        __syncthreads();
    }

    // ---- store K slice; cg 0 stores k ----
    {
        float* Kb = g_K + ((size_t)t * B_ + b) * (M_ * N_);
        for (int idx = tid; idx < 64 * 32; idx += 512) {
            int j = idx >> 5, cc = idx & 31;
            Kb[j * 128 + col0 + cc] = -sRb[j * 36 + cc];
        }
        if (cg == 0 && tid < 64) {
            float kv = -sRb[tid * 36 + 32];
            g_k[((size_t)t * B_ + b) * M_ + tid] = kv;
            sk[tid] = kv;
        }
    }
    __syncthreads();

    // ---- vn = qx + Qux^T k (cg 0 only) ----
    if (cg == 0 && tid < 128) {
        float acc = g_qhat[b * NT_ + tid];
#pragma unroll 8
        for (int m = 0; m < 64; m++) acc += Qub[m * NT_ + tid] * sk[m];
        g_v[b * 128 + tid] = acc;
    }

    // ---- Vn slice: Vn[:, col0..col0+31] = Qxx[:, cols] - Qux^T @ y(slice) ----
    {
        int tx = tid & 7;         // col strip: cols col0 + tx*4 .. +3
        int ty = tid >> 3;        // 0..63 -> rows ty*2, ty*2+1
        float acc2[2][4] = {};
#pragma unroll 4
        for (int m = 0; m < 64; m++) {
            float4 yv = *(const float4*)&sRb[m * 36 + tx * 4];
            const float* qrow = Qub + m * NT_ + ty * 2;
            float q0 = qrow[0], q1 = qrow[1];
            acc2[0][0] += q0 * yv.x; acc2[0][1] += q0 * yv.y;
            acc2[0][2] += q0 * yv.z; acc2[0][3] += q0 * yv.w;
            acc2[1][0] += q1 * yv.x; acc2[1][1] += q1 * yv.y;
            acc2[1][2] += q1 * yv.z; acc2[1][3] += q1 * yv.w;
        }
        const float* Qxxb = g_Qxx + b * N_ * N_;
        float* Vb = g_V + b * N_ * N_;
#pragma unroll
        for (int rr = 0; rr < 2; rr++) {
            int i = ty * 2 + rr;
            float4 q4 = *(const float4*)(Qxxb + i * N_ + col0 + tx * 4);
            *(float4*)(Vb + i * N_ + col0 + tx * 4) =
                make_float4(q4.x - acc2[rr][0], q4.y - acc2[rr][1],
                            q4.z - acc2[rr][2], q4.w - acc2[rr][3]);
        }
    }
}

// ---------------- forward rollout ----------------
__global__ __launch_bounds__(256) void kfwd(const float* __restrict__ A,
                                            const float* __restrict__ Bm,
                                            const float* __restrict__ c1,
                                            const float* __restrict__ xinit,
                                            float* __restrict__ out) {
    int b = blockIdx.x, tid = threadIdx.x;
    int warp = tid >> 5, lane = tid & 31;
    __shared__ float sx[128], su[64], sxn[128];
    if (tid < 128) sx[tid] = xinit[b * 128 + tid];
    __syncthreads();

    for (int t = 0; t < 128; t++) {
        size_t bt = (size_t)b * T_ + t;
        const float* Kb = g_K + ((size_t)t * B_ + b) * (M_ * N_);
        const float* kb = g_k + ((size_t)t * B_ + b) * M_;
        for (int r = warp; r < 64; r += 8) {
            const float* kr = Kb + r * 128;
            float s = kr[lane] * sx[lane] + kr[32 + lane] * sx[32 + lane]
                    + kr[64 + lane] * sx[64 + lane] + kr[96 + lane] * sx[96 + lane];
#pragma unroll
            for (int o = 16; o; o >>= 1) s += __shfl_down_sync(0xffffffffu, s, o);
            if (lane == 0) su[r] = s + kb[r];
        }
        if (tid < 128) out[bt * NT_ + tid] = sx[tid];
        __syncthreads();
        if (tid < 64) out[bt * NT_ + 128 + tid] = su[tid];

        const float* Ab = A + bt * (size_t)(N_ * N_);
        const float* Bb = Bm + bt * (size_t)(N_ * M_);
        for (int r = warp; r < 128; r += 8) {
            const float* ar = Ab + r * 128;
            const float* br = Bb + r * 64;
            float s = ar[lane] * sx[lane] + ar[32 + lane] * sx[32 + lane]
                    + ar[64 + lane] * sx[64 + lane] + ar[96 + lane] * sx[96 + lane]
                    + br[lane] * su[lane] + br[32 + lane] * su[32 + lane];
#pragma unroll
            for (int o = 16; o; o >>= 1) s += __shfl_down_sync(0xffffffffu, s, o);
            if (lane == 0) sxn[r] = s + c1[bt * 128 + r];
        }
        __syncthreads();
        if (tid < 128) sx[tid] = sxn[tid];
        __syncthreads();
    }
}

// ---------------- launch ----------------
extern "C" void kernel_launch(void* const* d_in, const int* in_sizes, int n_in,
                              void* d_out, int out_size) {
    const float *A = 0, *Bm = 0, *c1 = 0, *Q = 0, *p = 0, *xinit = 0;
    for (int i = 0; i < n_in; i++) {
        switch (in_sizes[i]) {
            case 67108864:  A = (const float*)d_in[i]; break;      // 32*128*128*128
            case 33554432:  Bm = (const float*)d_in[i]; break;     // 32*128*128*64
            case 524288:    c1 = (const float*)d_in[i]; break;     // 32*128*128
            case 150994944: Q = (const float*)d_in[i]; break;      // 32*128*192*192
            case 786432:    p = (const float*)d_in[i]; break;      // 32*128*192
            case 4096:      xinit = (const float*)d_in[i]; break;  // 32*128
        }
    }
    float* out = (float*)d_out;

    kzero<<<(B_ * N_ * N_ + 255) / 256, 256>>>();
    for (int t = T_ - 1; t >= 0; t--) {
        k1_VF<<<dim3(7, B_), 256>>>(A, Bm, c1, t);
        k2_Qhat<<<dim3(7, B_), 256>>>(A, Bm, Q, p, t);
        k3_solve<<<dim3(4, B_), 512>>>(t);
    }
    kfwd<<<B_, 256>>>(A, Bm, c1, xinit, out);
}